// round 11
// baseline (speedup 1.0000x reference)
#include <cuda_runtime.h>
#include <cuda_bf16.h>
#include <cstdint>

#define B_ 8
#define N_ 1024
#define H_ 8
#define D_ 32
#define XN (8192 * 256)
#define WN (256 * 768)

// split-bf16 QKV scratch: [s][b][h][n][d], Q pre-scaled by 1/sqrt(D)
#define QKV_ELEMS (3u * B_ * H_ * N_ * D_)
__device__ __nv_bfloat16 g_hi[QKV_ELEMS];
__device__ __nv_bfloat16 g_lo[QKV_ELEMS];
// split-bf16 GEMM operands
__device__ __nv_bfloat16 g_xh[XN], g_xl[XN];
__device__ __nv_bfloat16 g_wh[WN], g_wl[WN];

// ---------------------------------------------------------------------------
// PTX helpers
// ---------------------------------------------------------------------------
__device__ __forceinline__ uint32_t sptr(const void* p) {
    return (uint32_t)__cvta_generic_to_shared(p);
}
__device__ __forceinline__ void ldmx4(uint32_t* r, uint32_t a) {
    asm volatile("ldmatrix.sync.aligned.m8n8.x4.shared.b16 {%0,%1,%2,%3}, [%4];"
                 : "=r"(r[0]), "=r"(r[1]), "=r"(r[2]), "=r"(r[3]) : "r"(a));
}
__device__ __forceinline__ void ldmx4t(uint32_t* r, uint32_t a) {
    asm volatile("ldmatrix.sync.aligned.m8n8.x4.trans.shared.b16 {%0,%1,%2,%3}, [%4];"
                 : "=r"(r[0]), "=r"(r[1]), "=r"(r[2]), "=r"(r[3]) : "r"(a));
}
__device__ __forceinline__ void ldmx2t(uint32_t* r, uint32_t a) {
    asm volatile("ldmatrix.sync.aligned.m8n8.x2.trans.shared.b16 {%0,%1}, [%2];"
                 : "=r"(r[0]), "=r"(r[1]) : "r"(a));
}
__device__ __forceinline__ void mma_bf16(float* d, const uint32_t* a,
                                         uint32_t b0, uint32_t b1) {
    asm volatile("mma.sync.aligned.m16n8k16.row.col.f32.bf16.bf16.f32 "
                 "{%0,%1,%2,%3}, {%4,%5,%6,%7}, {%8,%9}, {%0,%1,%2,%3};"
                 : "+f"(d[0]), "+f"(d[1]), "+f"(d[2]), "+f"(d[3])
                 : "r"(a[0]), "r"(a[1]), "r"(a[2]), "r"(a[3]), "r"(b0), "r"(b1));
}
// pack two fp32 -> bf16x2 (first arg -> low half) — convention proven in R5
__device__ __forceinline__ uint32_t packbf(float lo, float hi) {
    uint32_t r;
    asm("cvt.rn.bf16x2.f32 %0, %1, %2;" : "=r"(r) : "f"(hi), "f"(lo));
    return r;
}
__device__ __forceinline__ float2 bf2f(uint32_t u) {
    __nv_bfloat162 t = *reinterpret_cast<__nv_bfloat162*>(&u);
    return __bfloat1622float2(t);
}
__device__ __forceinline__ void cpa16(uint32_t dst, const void* src) {
    asm volatile("cp.async.cg.shared.global [%0], [%1], 16;" :: "r"(dst), "l"(src));
}
#define CP_COMMIT asm volatile("cp.async.commit_group;")
#define CP_WAIT0  asm volatile("cp.async.wait_group 0;")
#define CP_WAIT1  asm volatile("cp.async.wait_group 1;")

// ---------------------------------------------------------------------------
// Kernel 0: split x and W into bf16 hi/lo.
// ---------------------------------------------------------------------------
__global__ __launch_bounds__(256) void split_xw(
    const float* __restrict__ x, const float* __restrict__ W)
{
    int i4 = (blockIdx.x * 256 + threadIdx.x) * 4;
    const float* src;
    __nv_bfloat16 *dh, *dl;
    int off;
    if (i4 < XN) {
        src = x; dh = g_xh; dl = g_xl; off = i4;
    } else {
        off = i4 - XN;
        if (off >= WN) return;
        src = W; dh = g_wh; dl = g_wl;
    }
    float4 v = *(const float4*)(src + off);
    uint32_t h01 = packbf(v.x, v.y), h23 = packbf(v.z, v.w);
    float2 f01 = bf2f(h01), f23 = bf2f(h23);
    *(uint2*)&dh[off] = make_uint2(h01, h23);
    *(uint2*)&dl[off] = make_uint2(packbf(v.x - f01.x, v.y - f01.y),
                                   packbf(v.z - f23.x, v.w - f23.y));
}

// ---------------------------------------------------------------------------
// Kernel 1: QKV projection via split-bf16 MMA, 3-stage cp.async pipeline.
// (unchanged from R7/R8)
// ---------------------------------------------------------------------------
__global__ __launch_bounds__(256) void qkv_gemm_mma(const float* __restrict__ bias)
{
    extern __shared__ __align__(16) unsigned char smg[];
    const int tid = threadIdx.x;
    const int w = tid >> 5, l = tid & 31;
    const int l16 = l & 15;
    const int mw = 32 * (w & 1);
    const int nw = 16 * (w >> 1);
    const int rb = blockIdx.y * 64;
    const int cb = blockIdx.x * 64;

    const int xrow = tid >> 2, xpart = tid & 3;
    const int wrow = tid >> 3, wpart = tid & 7;

    auto stage = [&](int k0, unsigned char* buf) {
        cpa16(sptr(buf + xrow * 80 + xpart * 16),
              g_xh + (size_t)(rb + xrow) * 256 + k0 + xpart * 8);
        cpa16(sptr(buf + 5120 + xrow * 80 + xpart * 16),
              g_xl + (size_t)(rb + xrow) * 256 + k0 + xpart * 8);
        cpa16(sptr(buf + 10240 + wrow * 144 + wpart * 16),
              g_wh + (size_t)(k0 + wrow) * 768 + cb + wpart * 8);
        cpa16(sptr(buf + 14848 + wrow * 144 + wpart * 16),
              g_wl + (size_t)(k0 + wrow) * 768 + cb + wpart * 8);
    };

    float acc[2][2][4] = {};

    stage(0, smg);            CP_COMMIT;
    stage(32, smg + 19456);   CP_COMMIT;

    for (int c = 0; c < 8; c++) {
        if (c < 7) { CP_WAIT1; } else { CP_WAIT0; }
        __syncthreads();
        if (c < 6) {
            stage((c + 2) * 32, smg + ((c + 2) % 3) * 19456);
            CP_COMMIT;
        }
        unsigned char* buf = smg + (c % 3) * 19456;
        const __nv_bfloat16* xh = (const __nv_bfloat16*)(buf);
        const __nv_bfloat16* xl = (const __nv_bfloat16*)(buf + 5120);
        const __nv_bfloat16* wh = (const __nv_bfloat16*)(buf + 10240);
        const __nv_bfloat16* wl = (const __nv_bfloat16*)(buf + 14848);

        #pragma unroll
        for (int ks = 0; ks < 2; ks++) {
            uint32_t ah[2][4], al[2][4];
            #pragma unroll
            for (int mf = 0; mf < 2; mf++) {
                int aoff = (mw + 16 * mf + l16) * 40 + ks * 16 + ((l & 16) >> 1);
                ldmx4(ah[mf], sptr(xh + aoff));
                ldmx4(al[mf], sptr(xl + aoff));
            }
            #pragma unroll
            for (int t = 0; t < 2; t++) {
                int woff = (ks * 16 + l16) * 72 + nw + 8 * t;
                uint32_t bh[2], bl[2];
                ldmx2t(bh, sptr(wh + woff));
                ldmx2t(bl, sptr(wl + woff));
                #pragma unroll
                for (int mf = 0; mf < 2; mf++) {
                    mma_bf16(acc[mf][t], ah[mf], bh[0], bh[1]);
                    mma_bf16(acc[mf][t], al[mf], bh[0], bh[1]);
                    mma_bf16(acc[mf][t], ah[mf], bl[0], bl[1]);
                }
            }
        }
    }

    #pragma unroll
    for (int t = 0; t < 2; t++) {
        int c0 = cb + nw + 8 * t + 2 * (l & 3);
        int s = c0 >> 8, rem = c0 & 255, h = rem >> 5, d = rem & 31;
        float sc = (s == 0) ? 0.17677669529663687f : 1.0f;
        float b0 = bias[c0], b1 = bias[c0 + 1];
        #pragma unroll
        for (int mf = 0; mf < 2; mf++) {
            #pragma unroll
            for (int rr = 0; rr < 2; rr++) {
                int r = rb + mw + 16 * mf + (l >> 2) + 8 * rr;
                int bq = r >> 10, n = r & 1023;
                float v0 = (acc[mf][t][2 * rr + 0] + b0) * sc;
                float v1 = (acc[mf][t][2 * rr + 1] + b1) * sc;
                uint32_t hv = packbf(v0, v1);
                float2 f = bf2f(hv);
                uint32_t lv = packbf(v0 - f.x, v1 - f.y);
                size_t idx = ((size_t)((s * 8 + bq) * 8 + h) * 1024 + n) * 32 + d;
                *(uint32_t*)&g_hi[idx] = hv;
                *(uint32_t*)&g_lo[idx] = lv;
            }
        }
    }
}

// ---------------------------------------------------------------------------
// Kernel 2: tensor-core moire attention. R7 base (2 CTAs/SM, persistent Q
// frags) + 128-key staging: barrier/wait once per TWO 64-key subtiles.
// FIX vs R9: n0k restored in K and V ldmatrix offsets.
// Dynamic smem = 8192 + 2 * 40960 = 90112 bytes.
// ---------------------------------------------------------------------------
__global__ __launch_bounds__(256, 2) void moire_attn(
    const float* __restrict__ adj, const unsigned int* __restrict__ mask,
    const float* __restrict__ shifts, const float* __restrict__ widths,
    const float* __restrict__ slw, float* __restrict__ out)
{
    extern __shared__ __align__(16) unsigned char smraw[];

    const int hh = blockIdx.x;
    const int q0 = blockIdx.y * 64;
    const int bb = blockIdx.z;
    const int tid = threadIdx.x;
    const int w   = tid >> 5;
    const int l   = tid & 31;
    const int wm  = w & 3;
    const int wk  = w >> 2;
    const int m0  = 16 * wm;
    const int n0k = 32 * wk;
    const int l16 = l & 15;
    const int qal = m0 + (l >> 2);
    const int qbl = qal + 8;

    const float sh   = shifts[hh];
    const float invw = 1.0f / fmaxf(widths[hh], 0.5f);
    const float sl   = slw[hh];
    const float LOGEPS = -13.815510557964274f;

    const size_t qbase = ((size_t)((0 * 8 + bb) * 8 + hh)) * 1024 * 32;
    const size_t kbase = ((size_t)((1 * 8 + bb) * 8 + hh)) * 1024 * 32;
    const size_t vbase = ((size_t)((2 * 8 + bb) * 8 + hh)) * 1024 * 32;

    __nv_bfloat16* Qh = (__nv_bfloat16*)(smraw);
    __nv_bfloat16* Ql = (__nv_bfloat16*)(smraw + 4096);

    // 128-row stage: Kh@0, Kl@10240, Vh@20480, Vl@30720 (pitch 80B), 40960B/stage
    auto stageKV = [&](int kb0, unsigned char* buf) {
        const int r2 = tid >> 1;
        const int p0 = (tid & 1) * 2;
        size_t gk = kbase + (size_t)(kb0 + r2) * 32;
        size_t gv = vbase + (size_t)(kb0 + r2) * 32;
        #pragma unroll
        for (int p = p0; p < p0 + 2; p++) {
            cpa16(sptr(buf + r2 * 80 + p * 16),         g_hi + gk + p * 8);
            cpa16(sptr(buf + 10240 + r2 * 80 + p * 16), g_lo + gk + p * 8);
            cpa16(sptr(buf + 20480 + r2 * 80 + p * 16), g_hi + gv + p * 8);
            cpa16(sptr(buf + 30720 + r2 * 80 + p * 16), g_lo + gv + p * 8);
        }
    };

    // stage Q (plain LDG) + prefetch stage 0 (keys 0..127)
    {
        const int row = tid >> 2, part = tid & 3;
        size_t gq = qbase + (size_t)(q0 + row) * 32 + part * 8;
        *(uint4*)(Qh + row * 32 + part * 8) = *(const uint4*)(g_hi + gq);
        *(uint4*)(Ql + row * 32 + part * 8) = *(const uint4*)(g_lo + gq);
    }
    stageKV(0, smraw + 8192);
    CP_COMMIT;

    const bool mqa = (mask[(size_t)bb * 1024 + q0 + qal] != 0u);
    const bool mqb = (mask[(size_t)bb * 1024 + q0 + qbl] != 0u);
    __syncthreads();

    // persistent Q fragments
    uint32_t qfh[2][4], qfl[2][4];
    #pragma unroll
    for (int ks = 0; ks < 2; ks++) {
        int off = (m0 + l16) * 32 + ks * 16 + ((l & 16) >> 1);
        ldmx4(qfh[ks], sptr(Qh + off));
        ldmx4(qfl[ks], sptr(Ql + off));
    }

    // V ldmatrix.x4.trans lane address components
    const int vmi = l >> 3, vr = l & 7;
    const int vrow_off = (vmi & 1) * 8 + vr;
    const int vcol_off = 8 * (vmi >> 1);

    float Oacc[4][4] = {};
    float lsa = 0.0f, lsb = 0.0f;

    // adj/mask prefetch registers (for the CURRENT subtile)
    float2 av[2][4];
    uint2  mkp[4];
    const float* apb = adj + ((size_t)(bb * 1024 + q0 + qal)) * 1024 + n0k + 2 * (l & 3);
    const unsigned int* mpb = mask + (size_t)bb * 1024 + n0k + 2 * (l & 3);
    #pragma unroll
    for (int t = 0; t < 4; t++) {
        av[0][t] = *(const float2*)(apb + 8 * t);
        av[1][t] = *(const float2*)(apb + 8 * 1024 + 8 * t);
        mkp[t]   = *(const uint2*)(mpb + 8 * t);
    }

    #pragma unroll 2
    for (int sub = 0; sub < 16; sub++) {
        const int kb = sub * 64;
        if ((sub & 1) == 0) {
            CP_WAIT0;          // stage sub/2 landed
            __syncthreads();   // all warps done with previous stage buffer
            if (sub < 14) {
                stageKV(kb + 128, smraw + 8192 + (((sub >> 1) + 1) & 1) * 40960);
                CP_COMMIT;
            }
        }
        unsigned char* stg = smraw + 8192 + ((sub >> 1) & 1) * 40960;
        const int soff = (sub & 1) * 5120;   // 64 rows * 80B into each matrix
        const __nv_bfloat16* Kh = (const __nv_bfloat16*)(stg + soff);
        const __nv_bfloat16* Kl = (const __nv_bfloat16*)(stg + 10240 + soff);
        const __nv_bfloat16* Vh = (const __nv_bfloat16*)(stg + 20480 + soff);
        const __nv_bfloat16* Vl = (const __nv_bfloat16*)(stg + 30720 + soff);

        // ---- QK: 4 n8-tile accumulators; K B-frags via ldmatrix.x4 ----
        float acc[4][4] = {};
        #pragma unroll
        for (int ks = 0; ks < 2; ks++) {
            #pragma unroll
            for (int t2 = 0; t2 < 2; t2++) {
                int koff = (n0k + 16 * t2 + l16) * 40 + ks * 16 + ((l & 16) >> 1);
                uint32_t rh[4], rl[4];
                ldmx4(rh, sptr(Kh + koff));
                ldmx4(rl, sptr(Kl + koff));
                mma_bf16(acc[2 * t2],     qfh[ks], rh[0], rh[2]);
                mma_bf16(acc[2 * t2],     qfl[ks], rh[0], rh[2]);
                mma_bf16(acc[2 * t2],     qfh[ks], rl[0], rl[2]);
                mma_bf16(acc[2 * t2 + 1], qfh[ks], rh[1], rh[3]);
                mma_bf16(acc[2 * t2 + 1], qfl[ks], rh[1], rh[3]);
                mma_bf16(acc[2 * t2 + 1], qfh[ks], rl[1], rl[3]);
            }
        }

        // ---- elementwise: moire + self-loop + mask + exp(val-12) ----
        const bool diag = (kb == q0);
        #pragma unroll
        for (int t = 0; t < 4; t++) {
            int c0 = n0k + 8 * t + 2 * (l & 3);     // within this 64-key subtile
            bool mk0 = (mkp[t].x != 0u), mk1 = (mkp[t].y != 0u);
            float ax = av[0][t].x - sh, ay = av[0][t].y - sh;
            float bx = av[1][t].x - sh, by = av[1][t].y - sh;
            float v00 = acc[t][0] + fmaxf(-ax * ax * invw, LOGEPS);
            float v01 = acc[t][1] + fmaxf(-ay * ay * invw, LOGEPS);
            float v10 = acc[t][2] + fmaxf(-bx * bx * invw, LOGEPS);
            float v11 = acc[t][3] + fmaxf(-by * by * invw, LOGEPS);
            if (diag) {
                if (qal == c0)     v00 += sl;
                if (qal == c0 + 1) v01 += sl;
                if (qbl == c0)     v10 += sl;
                if (qbl == c0 + 1) v11 += sl;
            }
            float w00 = mqa ? (mk0 ? __expf(v00 - 12.0f) : 0.0f) : 1.0f;
            float w01 = mqa ? (mk1 ? __expf(v01 - 12.0f) : 0.0f) : 1.0f;
            float w10 = mqb ? (mk0 ? __expf(v10 - 12.0f) : 0.0f) : 1.0f;
            float w11 = mqb ? (mk1 ? __expf(v11 - 12.0f) : 0.0f) : 1.0f;
            lsa += w00 + w01;
            lsb += w10 + w11;
            acc[t][0] = w00; acc[t][1] = w01; acc[t][2] = w10; acc[t][3] = w11;
        }

        // ---- prefetch adj/mask for NEXT subtile (covered by P-pack + PV) ----
        if (sub < 15) {
            const float* ap = apb + (size_t)(kb + 64);
            const unsigned int* mp = mpb + kb + 64;
            #pragma unroll
            for (int t = 0; t < 4; t++) {
                av[0][t] = *(const float2*)(ap + 8 * t);
                av[1][t] = *(const float2*)(ap + 8 * 1024 + 8 * t);
                mkp[t]   = *(const uint2*)(mp + 8 * t);
            }
        }

        // ---- P fragments (accumulator layout == A-fragment layout) ----
        uint32_t pfh[2][4], pfl[2][4];
        #pragma unroll
        for (int cch = 0; cch < 2; cch++) {
            #pragma unroll
            for (int rr = 0; rr < 2; rr++) {
                const float* a4 = acc[2 * cch + rr];
                uint32_t u0 = packbf(a4[0], a4[1]);
                uint32_t u1 = packbf(a4[2], a4[3]);
                float2 f0 = bf2f(u0), f1 = bf2f(u1);
                pfh[cch][rr * 2 + 0] = u0;
                pfh[cch][rr * 2 + 1] = u1;
                pfl[cch][rr * 2 + 0] = packbf(a4[0] - f0.x, a4[1] - f0.y);
                pfl[cch][rr * 2 + 1] = packbf(a4[2] - f1.x, a4[3] - f1.y);
            }
        }

        // ---- PV: O += Ph@Vh + Pl@Vh + Ph@Vl; V frags via x4.trans ----
        #pragma unroll
        for (int cch = 0; cch < 2; cch++) {
            #pragma unroll
            for (int tdp = 0; tdp < 2; tdp++) {
                int voff = (n0k + 16 * cch + vrow_off) * 40 + 8 * (2 * tdp) + vcol_off;
                uint32_t rvh[4], rvl[4];
                ldmx4t(rvh, sptr(Vh + voff));
                ldmx4t(rvl, sptr(Vl + voff));
                mma_bf16(Oacc[2 * tdp],     pfh[cch], rvh[0], rvh[1]);
                mma_bf16(Oacc[2 * tdp],     pfl[cch], rvh[0], rvh[1]);
                mma_bf16(Oacc[2 * tdp],     pfh[cch], rvl[0], rvl[1]);
                mma_bf16(Oacc[2 * tdp + 1], pfh[cch], rvh[2], rvh[3]);
                mma_bf16(Oacc[2 * tdp + 1], pfl[cch], rvh[2], rvh[3]);
                mma_bf16(Oacc[2 * tdp + 1], pfh[cch], rvl[2], rvl[3]);
            }
        }
    }

    // ---- lsum: zero (overlay on stage area), reduce, accumulate ----
    __syncthreads();
    float* lsum = (float*)(smraw + 8192);
    if (tid < 64) lsum[tid] = 0.0f;
    __syncthreads();
    lsa += __shfl_xor_sync(0xffffffffu, lsa, 1);
    lsa += __shfl_xor_sync(0xffffffffu, lsa, 2);
    lsb += __shfl_xor_sync(0xffffffffu, lsb, 1);
    lsb += __shfl_xor_sync(0xffffffffu, lsb, 2);
    if ((l & 3) == 0) {
        atomicAdd(&lsum[qal], lsa);
        atomicAdd(&lsum[qbl], lsb);
    }

    // ---- combine wk halves via Obuf (overlays Qh/Ql) and write out ----
    float* Obuf = (float*)smraw;  // 64 x 32 floats = 8KB
    if (wk == 1) {
        #pragma unroll
        for (int td = 0; td < 4; td++) {
            int n = 8 * td + 2 * (l & 3);
            *(float2*)&Obuf[qal * 32 + n] = make_float2(Oacc[td][0], Oacc[td][1]);
            *(float2*)&Obuf[qbl * 32 + n] = make_float2(Oacc[td][2], Oacc[td][3]);
        }
    }
    __syncthreads();
    if (wk == 0) {
        float rla = 1.0f / lsum[qal];
        float rlb = 1.0f / lsum[qbl];
        #pragma unroll
        for (int td = 0; td < 4; td++) {
            int n = 8 * td + 2 * (l & 3);
            float2 oa = *(const float2*)&Obuf[qal * 32 + n];
            float2 ob = *(const float2*)&Obuf[qbl * 32 + n];
            oa.x = (oa.x + Oacc[td][0]) * rla;
            oa.y = (oa.y + Oacc[td][1]) * rla;
            ob.x = (ob.x + Oacc[td][2]) * rlb;
            ob.y = (ob.y + Oacc[td][3]) * rlb;
            *(float2*)&out[((size_t)bb * 1024 + q0 + qal) * 256 + hh * 32 + n] = oa;
            *(float2*)&out[((size_t)bb * 1024 + q0 + qbl) * 256 + hh * 32 + n] = ob;
        }
    }
}

// ---------------------------------------------------------------------------
// Launch. Inputs: x, adj, mask, W_qkv, b_qkv, shifts, widths, self_loop_w
// ---------------------------------------------------------------------------
extern "C" void kernel_launch(void* const* d_in, const int* in_sizes, int n_in,
                              void* d_out, int out_size)
{
    const float*        x      = (const float*)d_in[0];
    const float*        adj    = (const float*)d_in[1];
    const unsigned int* mask   = (const unsigned int*)d_in[2];
    const float*        W_qkv  = (const float*)d_in[3];
    const float*        b_qkv  = (const float*)d_in[4];
    const float*        shifts = (const float*)d_in[5];
    const float*        widths = (const float*)d_in[6];
    const float*        slw    = (const float*)d_in[7];
    float*              out    = (float*)d_out;

    static bool attr_done = false;
    if (!attr_done) {
        cudaFuncSetAttribute(qkv_gemm_mma,
            cudaFuncAttributeMaxDynamicSharedMemorySize, 3 * 19456);
        cudaFuncSetAttribute(moire_attn,
            cudaFuncAttributeMaxDynamicSharedMemorySize, 8192 + 2 * 40960);
        attr_done = true;
    }

    split_xw<<<(XN + WN) / 1024, 256>>>(x, W_qkv);
    qkv_gemm_mma<<<dim3(12, 128), 256, 3 * 19456>>>(b_qkv);
    moire_attn<<<dim3(8, 16, 8), 256, 8192 + 2 * 40960>>>(
        adj, mask, shifts, widths, slw, out);
}

// round 12
// speedup vs baseline: 1.1386x; 1.1386x over previous
#include <cuda_runtime.h>
#include <cuda_bf16.h>
#include <cstdint>

#define B_ 8
#define N_ 1024
#define H_ 8
#define D_ 32
#define XN (8192 * 256)
#define WN (256 * 768)

// split-bf16 QKV scratch: [s][b][h][n][d], Q pre-scaled by 1/sqrt(D)
#define QKV_ELEMS (3u * B_ * H_ * N_ * D_)
__device__ __nv_bfloat16 g_hi[QKV_ELEMS];
__device__ __nv_bfloat16 g_lo[QKV_ELEMS];
// split-bf16 GEMM operands
__device__ __nv_bfloat16 g_xh[XN], g_xl[XN];
__device__ __nv_bfloat16 g_wh[WN], g_wl[WN];

// ---------------------------------------------------------------------------
// PTX helpers
// ---------------------------------------------------------------------------
__device__ __forceinline__ uint32_t sptr(const void* p) {
    return (uint32_t)__cvta_generic_to_shared(p);
}
__device__ __forceinline__ void ldmx4(uint32_t* r, uint32_t a) {
    asm volatile("ldmatrix.sync.aligned.m8n8.x4.shared.b16 {%0,%1,%2,%3}, [%4];"
                 : "=r"(r[0]), "=r"(r[1]), "=r"(r[2]), "=r"(r[3]) : "r"(a));
}
__device__ __forceinline__ void ldmx4t(uint32_t* r, uint32_t a) {
    asm volatile("ldmatrix.sync.aligned.m8n8.x4.trans.shared.b16 {%0,%1,%2,%3}, [%4];"
                 : "=r"(r[0]), "=r"(r[1]), "=r"(r[2]), "=r"(r[3]) : "r"(a));
}
__device__ __forceinline__ void ldmx2t(uint32_t* r, uint32_t a) {
    asm volatile("ldmatrix.sync.aligned.m8n8.x2.trans.shared.b16 {%0,%1}, [%2];"
                 : "=r"(r[0]), "=r"(r[1]) : "r"(a));
}
__device__ __forceinline__ void mma_bf16(float* d, const uint32_t* a,
                                         uint32_t b0, uint32_t b1) {
    asm volatile("mma.sync.aligned.m16n8k16.row.col.f32.bf16.bf16.f32 "
                 "{%0,%1,%2,%3}, {%4,%5,%6,%7}, {%8,%9}, {%0,%1,%2,%3};"
                 : "+f"(d[0]), "+f"(d[1]), "+f"(d[2]), "+f"(d[3])
                 : "r"(a[0]), "r"(a[1]), "r"(a[2]), "r"(a[3]), "r"(b0), "r"(b1));
}
// pack two fp32 -> bf16x2 (first arg -> low half) — convention proven in R5
__device__ __forceinline__ uint32_t packbf(float lo, float hi) {
    uint32_t r;
    asm("cvt.rn.bf16x2.f32 %0, %1, %2;" : "=r"(r) : "f"(hi), "f"(lo));
    return r;
}
__device__ __forceinline__ float2 bf2f(uint32_t u) {
    __nv_bfloat162 t = *reinterpret_cast<__nv_bfloat162*>(&u);
    return __bfloat1622float2(t);
}
__device__ __forceinline__ void cpa16(uint32_t dst, const void* src) {
    asm volatile("cp.async.cg.shared.global [%0], [%1], 16;" :: "r"(dst), "l"(src));
}
#define CP_COMMIT asm volatile("cp.async.commit_group;")
#define CP_WAIT0  asm volatile("cp.async.wait_group 0;")
#define CP_WAIT1  asm volatile("cp.async.wait_group 1;")

// ---------------------------------------------------------------------------
// Kernel 0: split x and W into bf16 hi/lo.
// ---------------------------------------------------------------------------
__global__ __launch_bounds__(256) void split_xw(
    const float* __restrict__ x, const float* __restrict__ W)
{
    int i4 = (blockIdx.x * 256 + threadIdx.x) * 4;
    const float* src;
    __nv_bfloat16 *dh, *dl;
    int off;
    if (i4 < XN) {
        src = x; dh = g_xh; dl = g_xl; off = i4;
    } else {
        off = i4 - XN;
        if (off >= WN) return;
        src = W; dh = g_wh; dl = g_wl;
    }
    float4 v = *(const float4*)(src + off);
    uint32_t h01 = packbf(v.x, v.y), h23 = packbf(v.z, v.w);
    float2 f01 = bf2f(h01), f23 = bf2f(h23);
    *(uint2*)&dh[off] = make_uint2(h01, h23);
    *(uint2*)&dl[off] = make_uint2(packbf(v.x - f01.x, v.y - f01.y),
                                   packbf(v.z - f23.x, v.w - f23.y));
}

// ---------------------------------------------------------------------------
// Kernel 1: QKV projection via split-bf16 MMA, 3-stage cp.async pipeline.
// (unchanged from R7)
// ---------------------------------------------------------------------------
__global__ __launch_bounds__(256) void qkv_gemm_mma(const float* __restrict__ bias)
{
    extern __shared__ __align__(16) unsigned char smg[];
    const int tid = threadIdx.x;
    const int w = tid >> 5, l = tid & 31;
    const int l16 = l & 15;
    const int mw = 32 * (w & 1);
    const int nw = 16 * (w >> 1);
    const int rb = blockIdx.y * 64;
    const int cb = blockIdx.x * 64;

    const int xrow = tid >> 2, xpart = tid & 3;
    const int wrow = tid >> 3, wpart = tid & 7;

    auto stage = [&](int k0, unsigned char* buf) {
        cpa16(sptr(buf + xrow * 80 + xpart * 16),
              g_xh + (size_t)(rb + xrow) * 256 + k0 + xpart * 8);
        cpa16(sptr(buf + 5120 + xrow * 80 + xpart * 16),
              g_xl + (size_t)(rb + xrow) * 256 + k0 + xpart * 8);
        cpa16(sptr(buf + 10240 + wrow * 144 + wpart * 16),
              g_wh + (size_t)(k0 + wrow) * 768 + cb + wpart * 8);
        cpa16(sptr(buf + 14848 + wrow * 144 + wpart * 16),
              g_wl + (size_t)(k0 + wrow) * 768 + cb + wpart * 8);
    };

    float acc[2][2][4] = {};

    stage(0, smg);            CP_COMMIT;
    stage(32, smg + 19456);   CP_COMMIT;

    for (int c = 0; c < 8; c++) {
        if (c < 7) { CP_WAIT1; } else { CP_WAIT0; }
        __syncthreads();
        if (c < 6) {
            stage((c + 2) * 32, smg + ((c + 2) % 3) * 19456);
            CP_COMMIT;
        }
        unsigned char* buf = smg + (c % 3) * 19456;
        const __nv_bfloat16* xh = (const __nv_bfloat16*)(buf);
        const __nv_bfloat16* xl = (const __nv_bfloat16*)(buf + 5120);
        const __nv_bfloat16* wh = (const __nv_bfloat16*)(buf + 10240);
        const __nv_bfloat16* wl = (const __nv_bfloat16*)(buf + 14848);

        #pragma unroll
        for (int ks = 0; ks < 2; ks++) {
            uint32_t ah[2][4], al[2][4];
            #pragma unroll
            for (int mf = 0; mf < 2; mf++) {
                int aoff = (mw + 16 * mf + l16) * 40 + ks * 16 + ((l & 16) >> 1);
                ldmx4(ah[mf], sptr(xh + aoff));
                ldmx4(al[mf], sptr(xl + aoff));
            }
            #pragma unroll
            for (int t = 0; t < 2; t++) {
                int woff = (ks * 16 + l16) * 72 + nw + 8 * t;
                uint32_t bh[2], bl[2];
                ldmx2t(bh, sptr(wh + woff));
                ldmx2t(bl, sptr(wl + woff));
                #pragma unroll
                for (int mf = 0; mf < 2; mf++) {
                    mma_bf16(acc[mf][t], ah[mf], bh[0], bh[1]);
                    mma_bf16(acc[mf][t], al[mf], bh[0], bh[1]);
                    mma_bf16(acc[mf][t], ah[mf], bl[0], bl[1]);
                }
            }
        }
    }

    #pragma unroll
    for (int t = 0; t < 2; t++) {
        int c0 = cb + nw + 8 * t + 2 * (l & 3);
        int s = c0 >> 8, rem = c0 & 255, h = rem >> 5, d = rem & 31;
        float sc = (s == 0) ? 0.17677669529663687f : 1.0f;
        float b0 = bias[c0], b1 = bias[c0 + 1];
        #pragma unroll
        for (int mf = 0; mf < 2; mf++) {
            #pragma unroll
            for (int rr = 0; rr < 2; rr++) {
                int r = rb + mw + 16 * mf + (l >> 2) + 8 * rr;
                int bq = r >> 10, n = r & 1023;
                float v0 = (acc[mf][t][2 * rr + 0] + b0) * sc;
                float v1 = (acc[mf][t][2 * rr + 1] + b1) * sc;
                uint32_t hv = packbf(v0, v1);
                float2 f = bf2f(hv);
                uint32_t lv = packbf(v0 - f.x, v1 - f.y);
                size_t idx = ((size_t)((s * 8 + bq) * 8 + h) * 1024 + n) * 32 + d;
                *(uint32_t*)&g_hi[idx] = hv;
                *(uint32_t*)&g_lo[idx] = lv;
            }
        }
    }
}

// ---------------------------------------------------------------------------
// Kernel 2: tensor-core moire attention — exact R7 structure (best measured:
// 3-stage 64-key pipeline, one sync/iter, persistent Q frags, x4.trans V),
// plus mask folded into the exp argument:
//   kb = mk ? -12 : -1000012 (per column), fq in {0,1} (per row)
//   w  = expf(fq * (val + kb))   -> identical values, fewer selects.
// Dynamic smem = 8192 + 3 * 20480 = 69632 bytes.
// ---------------------------------------------------------------------------
__global__ __launch_bounds__(256, 2) void moire_attn(
    const float* __restrict__ adj, const unsigned int* __restrict__ mask,
    const float* __restrict__ shifts, const float* __restrict__ widths,
    const float* __restrict__ slw, float* __restrict__ out)
{
    extern __shared__ __align__(16) unsigned char smraw[];

    const int hh = blockIdx.x;
    const int q0 = blockIdx.y * 64;
    const int bb = blockIdx.z;
    const int tid = threadIdx.x;
    const int w   = tid >> 5;
    const int l   = tid & 31;
    const int wm  = w & 3;
    const int wk  = w >> 2;
    const int m0  = 16 * wm;
    const int n0k = 32 * wk;
    const int l16 = l & 15;
    const int qal = m0 + (l >> 2);
    const int qbl = qal + 8;

    const float sh   = shifts[hh];
    const float invw = 1.0f / fmaxf(widths[hh], 0.5f);
    const float sl   = slw[hh];
    const float LOGEPS = -13.815510557964274f;

    const size_t qbase = ((size_t)((0 * 8 + bb) * 8 + hh)) * 1024 * 32;
    const size_t kbase = ((size_t)((1 * 8 + bb) * 8 + hh)) * 1024 * 32;
    const size_t vbase = ((size_t)((2 * 8 + bb) * 8 + hh)) * 1024 * 32;

    __nv_bfloat16* Qh = (__nv_bfloat16*)(smraw);
    __nv_bfloat16* Ql = (__nv_bfloat16*)(smraw + 4096);

    const int row = tid >> 2, part = tid & 3;

    auto stageKV = [&](int kb, unsigned char* buf) {
        size_t gk = kbase + (size_t)(kb + row) * 32 + part * 8;
        size_t gv = vbase + (size_t)(kb + row) * 32 + part * 8;
        cpa16(sptr(buf + row * 80 + part * 16),         g_hi + gk);
        cpa16(sptr(buf + 5120 + row * 80 + part * 16),  g_lo + gk);
        cpa16(sptr(buf + 10240 + row * 80 + part * 16), g_hi + gv);
        cpa16(sptr(buf + 15360 + row * 80 + part * 16), g_lo + gv);
    };

    // stage Q (plain LDG) + prefetch stages 0,1 of K/V
    {
        size_t gq = qbase + (size_t)(q0 + row) * 32 + part * 8;
        *(uint4*)(Qh + row * 32 + part * 8) = *(const uint4*)(g_hi + gq);
        *(uint4*)(Ql + row * 32 + part * 8) = *(const uint4*)(g_lo + gq);
    }
    stageKV(0, smraw + 8192);            CP_COMMIT;
    stageKV(64, smraw + 8192 + 20480);   CP_COMMIT;

    const float fqa = (mask[(size_t)bb * 1024 + q0 + qal] != 0u) ? 1.0f : 0.0f;
    const float fqb = (mask[(size_t)bb * 1024 + q0 + qbl] != 0u) ? 1.0f : 0.0f;
    __syncthreads();

    uint32_t qfh[2][4], qfl[2][4];
    #pragma unroll
    for (int ks = 0; ks < 2; ks++) {
        int off = (m0 + l16) * 32 + ks * 16 + ((l & 16) >> 1);
        ldmx4(qfh[ks], sptr(Qh + off));
        ldmx4(qfl[ks], sptr(Ql + off));
    }

    // V ldmatrix.x4.trans lane address components
    const int vmi = l >> 3, vr = l & 7;
    const int vrow_off = (vmi & 1) * 8 + vr;     // k within 16
    const int vcol_off = 8 * (vmi >> 1);         // second n8 tile select

    float Oacc[4][4] = {};
    float lsa = 0.0f, lsb = 0.0f;

    for (int it = 0; it < 16; it++) {
        const int kb = it * 64;
        // adj + mask prefetch (regs; overlaps pipeline drain)
        float2 av[2][4];
        uint2  mkp[4];
        {
            const float* ap = adj + ((size_t)(bb * 1024 + q0 + qal)) * 1024
                              + kb + n0k + 2 * (l & 3);
            const unsigned int* mp = mask + (size_t)bb * 1024 + kb + n0k + 2 * (l & 3);
            #pragma unroll
            for (int t = 0; t < 4; t++) {
                av[0][t] = *(const float2*)(ap + 8 * t);
                av[1][t] = *(const float2*)(ap + 8 * 1024 + 8 * t);
                mkp[t]   = *(const uint2*)(mp + 8 * t);
            }
        }
        if (it < 15) { CP_WAIT1; } else { CP_WAIT0; }
        __syncthreads();   // stage `it` visible to all; iter it-1 reads done
        if (it < 14) {
            // writes buffer (it+2)%3, last read in iter it-1 -> safe after sync
            stageKV(kb + 128, smraw + 8192 + ((it + 2) % 3) * 20480);
            CP_COMMIT;
        }

        unsigned char* buf = smraw + 8192 + (it % 3) * 20480;
        const __nv_bfloat16* Kh = (const __nv_bfloat16*)(buf);
        const __nv_bfloat16* Kl = (const __nv_bfloat16*)(buf + 5120);
        const __nv_bfloat16* Vh = (const __nv_bfloat16*)(buf + 10240);
        const __nv_bfloat16* Vl = (const __nv_bfloat16*)(buf + 15360);

        // ---- QK: 4 n8-tile accumulators; K B-frags via ldmatrix.x4 ----
        float acc[4][4] = {};
        #pragma unroll
        for (int ks = 0; ks < 2; ks++) {
            #pragma unroll
            for (int t2 = 0; t2 < 2; t2++) {
                int koff = (n0k + 16 * t2 + l16) * 40 + ks * 16 + ((l & 16) >> 1);
                uint32_t rh[4], rl[4];
                ldmx4(rh, sptr(Kh + koff));
                ldmx4(rl, sptr(Kl + koff));
                mma_bf16(acc[2 * t2],     qfh[ks], rh[0], rh[2]);
                mma_bf16(acc[2 * t2],     qfl[ks], rh[0], rh[2]);
                mma_bf16(acc[2 * t2],     qfh[ks], rl[0], rl[2]);
                mma_bf16(acc[2 * t2 + 1], qfh[ks], rh[1], rh[3]);
                mma_bf16(acc[2 * t2 + 1], qfl[ks], rh[1], rh[3]);
                mma_bf16(acc[2 * t2 + 1], qfh[ks], rl[1], rl[3]);
            }
        }

        // ---- elementwise: moire + self-loop + folded mask + exp ----
        const bool diag = (kb == q0);
        #pragma unroll
        for (int t = 0; t < 4; t++) {
            int c0 = n0k + 8 * t + 2 * (l & 3);
            // column bias: -12 if key valid, -1000012 if masked (shared by 2 rows)
            float kb0 = (mkp[t].x != 0u) ? -12.0f : -1000012.0f;
            float kb1 = (mkp[t].y != 0u) ? -12.0f : -1000012.0f;
            float ax = av[0][t].x - sh, ay = av[0][t].y - sh;
            float bx = av[1][t].x - sh, by = av[1][t].y - sh;
            float v00 = acc[t][0] + fmaxf(-ax * ax * invw, LOGEPS);
            float v01 = acc[t][1] + fmaxf(-ay * ay * invw, LOGEPS);
            float v10 = acc[t][2] + fmaxf(-bx * bx * invw, LOGEPS);
            float v11 = acc[t][3] + fmaxf(-by * by * invw, LOGEPS);
            if (diag) {
                if (qal == c0)     v00 += sl;
                if (qal == c0 + 1) v01 += sl;
                if (qbl == c0)     v10 += sl;
                if (qbl == c0 + 1) v11 += sl;
            }
            // w = exp(fq * (val + kb)): valid -> exp(val-12); masked-k -> 0;
            // masked-q row -> exp(0) = 1 (uniform, matches reference softmax)
            float w00 = __expf(fqa * (v00 + kb0));
            float w01 = __expf(fqa * (v01 + kb1));
            float w10 = __expf(fqb * (v10 + kb0));
            float w11 = __expf(fqb * (v11 + kb1));
            lsa += w00 + w01;
            lsb += w10 + w11;
            acc[t][0] = w00; acc[t][1] = w01; acc[t][2] = w10; acc[t][3] = w11;
        }

        // ---- P fragments (accumulator layout == A-fragment layout) ----
        uint32_t pfh[2][4], pfl[2][4];
        #pragma unroll
        for (int cch = 0; cch < 2; cch++) {
            #pragma unroll
            for (int rr = 0; rr < 2; rr++) {
                const float* a4 = acc[2 * cch + rr];
                uint32_t u0 = packbf(a4[0], a4[1]);
                uint32_t u1 = packbf(a4[2], a4[3]);
                float2 f0 = bf2f(u0), f1 = bf2f(u1);
                pfh[cch][rr * 2 + 0] = u0;
                pfh[cch][rr * 2 + 1] = u1;
                pfl[cch][rr * 2 + 0] = packbf(a4[0] - f0.x, a4[1] - f0.y);
                pfl[cch][rr * 2 + 1] = packbf(a4[2] - f1.x, a4[3] - f1.y);
            }
        }

        // ---- PV: O += Ph@Vh + Pl@Vh + Ph@Vl; V frags via x4.trans ----
        #pragma unroll
        for (int cch = 0; cch < 2; cch++) {
            #pragma unroll
            for (int tdp = 0; tdp < 2; tdp++) {
                int voff = (n0k + 16 * cch + vrow_off) * 40 + 8 * (2 * tdp) + vcol_off;
                uint32_t rvh[4], rvl[4];
                ldmx4t(rvh, sptr(Vh + voff));
                ldmx4t(rvl, sptr(Vl + voff));
                mma_bf16(Oacc[2 * tdp],     pfh[cch], rvh[0], rvh[1]);
                mma_bf16(Oacc[2 * tdp],     pfl[cch], rvh[0], rvh[1]);
                mma_bf16(Oacc[2 * tdp],     pfh[cch], rvl[0], rvl[1]);
                mma_bf16(Oacc[2 * tdp + 1], pfh[cch], rvh[2], rvh[3]);
                mma_bf16(Oacc[2 * tdp + 1], pfl[cch], rvh[2], rvh[3]);
                mma_bf16(Oacc[2 * tdp + 1], pfh[cch], rvl[2], rvl[3]);
            }
        }
    }

    // ---- lsum: zero (overlay on stage area), reduce, accumulate ----
    __syncthreads();
    float* lsum = (float*)(smraw + 8192);
    if (tid < 64) lsum[tid] = 0.0f;
    __syncthreads();
    lsa += __shfl_xor_sync(0xffffffffu, lsa, 1);
    lsa += __shfl_xor_sync(0xffffffffu, lsa, 2);
    lsb += __shfl_xor_sync(0xffffffffu, lsb, 1);
    lsb += __shfl_xor_sync(0xffffffffu, lsb, 2);
    if ((l & 3) == 0) {
        atomicAdd(&lsum[qal], lsa);
        atomicAdd(&lsum[qbl], lsb);
    }

    // ---- combine wk halves via Obuf (overlays Qh/Ql) and write out ----
    float* Obuf = (float*)smraw;  // 64 x 32 floats = 8KB
    if (wk == 1) {
        #pragma unroll
        for (int td = 0; td < 4; td++) {
            int n = 8 * td + 2 * (l & 3);
            *(float2*)&Obuf[qal * 32 + n] = make_float2(Oacc[td][0], Oacc[td][1]);
            *(float2*)&Obuf[qbl * 32 + n] = make_float2(Oacc[td][2], Oacc[td][3]);
        }
    }
    __syncthreads();
    if (wk == 0) {
        float rla = 1.0f / lsum[qal];
        float rlb = 1.0f / lsum[qbl];
        #pragma unroll
        for (int td = 0; td < 4; td++) {
            int n = 8 * td + 2 * (l & 3);
            float2 oa = *(const float2*)&Obuf[qal * 32 + n];
            float2 ob = *(const float2*)&Obuf[qbl * 32 + n];
            oa.x = (oa.x + Oacc[td][0]) * rla;
            oa.y = (oa.y + Oacc[td][1]) * rla;
            ob.x = (ob.x + Oacc[td][2]) * rlb;
            ob.y = (ob.y + Oacc[td][3]) * rlb;
            *(float2*)&out[((size_t)bb * 1024 + q0 + qal) * 256 + hh * 32 + n] = oa;
            *(float2*)&out[((size_t)bb * 1024 + q0 + qbl) * 256 + hh * 32 + n] = ob;
        }
    }
}

// ---------------------------------------------------------------------------
// Launch. Inputs: x, adj, mask, W_qkv, b_qkv, shifts, widths, self_loop_w
// ---------------------------------------------------------------------------
extern "C" void kernel_launch(void* const* d_in, const int* in_sizes, int n_in,
                              void* d_out, int out_size)
{
    const float*        x      = (const float*)d_in[0];
    const float*        adj    = (const float*)d_in[1];
    const unsigned int* mask   = (const unsigned int*)d_in[2];
    const float*        W_qkv  = (const float*)d_in[3];
    const float*        b_qkv  = (const float*)d_in[4];
    const float*        shifts = (const float*)d_in[5];
    const float*        widths = (const float*)d_in[6];
    const float*        slw    = (const float*)d_in[7];
    float*              out    = (float*)d_out;

    static bool attr_done = false;
    if (!attr_done) {
        cudaFuncSetAttribute(qkv_gemm_mma,
            cudaFuncAttributeMaxDynamicSharedMemorySize, 3 * 19456);
        cudaFuncSetAttribute(moire_attn,
            cudaFuncAttributeMaxDynamicSharedMemorySize, 8192 + 3 * 20480);
        attr_done = true;
    }

    split_xw<<<(XN + WN) / 1024, 256>>>(x, W_qkv);
    qkv_gemm_mma<<<dim3(12, 128), 256, 3 * 19456>>>(b_qkv);
    moire_attn<<<dim3(8, 16, 8), 256, 8192 + 3 * 20480>>>(
        adj, mask, shifts, widths, slw, out);
}

// round 14
// speedup vs baseline: 1.3054x; 1.1465x over previous
#include <cuda_runtime.h>
#include <cuda_bf16.h>
#include <cuda_fp16.h>
#include <cstdint>

#define B_ 8
#define N_ 1024
#define H_ 8
#define D_ 32
#define XN (8192 * 256)
#define WN (256 * 768)

// split-bf16 Q/K scratch: [s][b][h][n][d], Q pre-scaled by log2(e)/sqrt(D)
#define QKV_ELEMS (3u * B_ * H_ * N_ * D_)
__device__ __nv_bfloat16 g_hi[QKV_ELEMS];
__device__ __nv_bfloat16 g_lo[QKV_ELEMS];
// V scratch: plain fp16
__device__ __half g_v16[B_ * H_ * N_ * D_];
// split-bf16 GEMM operands
__device__ __nv_bfloat16 g_xh[XN], g_xl[XN];
__device__ __nv_bfloat16 g_wh[WN], g_wl[WN];

// ---------------------------------------------------------------------------
// PTX helpers
// ---------------------------------------------------------------------------
__device__ __forceinline__ uint32_t sptr(const void* p) {
    return (uint32_t)__cvta_generic_to_shared(p);
}
__device__ __forceinline__ void ldmx4(uint32_t* r, uint32_t a) {
    asm volatile("ldmatrix.sync.aligned.m8n8.x4.shared.b16 {%0,%1,%2,%3}, [%4];"
                 : "=r"(r[0]), "=r"(r[1]), "=r"(r[2]), "=r"(r[3]) : "r"(a));
}
__device__ __forceinline__ void ldmx4t(uint32_t* r, uint32_t a) {
    asm volatile("ldmatrix.sync.aligned.m8n8.x4.trans.shared.b16 {%0,%1,%2,%3}, [%4];"
                 : "=r"(r[0]), "=r"(r[1]), "=r"(r[2]), "=r"(r[3]) : "r"(a));
}
__device__ __forceinline__ void ldmx2t(uint32_t* r, uint32_t a) {
    asm volatile("ldmatrix.sync.aligned.m8n8.x2.trans.shared.b16 {%0,%1}, [%2];"
                 : "=r"(r[0]), "=r"(r[1]) : "r"(a));
}
__device__ __forceinline__ void mma_bf16(float* d, const uint32_t* a,
                                         uint32_t b0, uint32_t b1) {
    asm volatile("mma.sync.aligned.m16n8k16.row.col.f32.bf16.bf16.f32 "
                 "{%0,%1,%2,%3}, {%4,%5,%6,%7}, {%8,%9}, {%0,%1,%2,%3};"
                 : "+f"(d[0]), "+f"(d[1]), "+f"(d[2]), "+f"(d[3])
                 : "r"(a[0]), "r"(a[1]), "r"(a[2]), "r"(a[3]), "r"(b0), "r"(b1));
}
__device__ __forceinline__ void mma_f16(float* d, const uint32_t* a,
                                        uint32_t b0, uint32_t b1) {
    asm volatile("mma.sync.aligned.m16n8k16.row.col.f32.f16.f16.f32 "
                 "{%0,%1,%2,%3}, {%4,%5,%6,%7}, {%8,%9}, {%0,%1,%2,%3};"
                 : "+f"(d[0]), "+f"(d[1]), "+f"(d[2]), "+f"(d[3])
                 : "r"(a[0]), "r"(a[1]), "r"(a[2]), "r"(a[3]), "r"(b0), "r"(b1));
}
// pack two fp32 -> bf16x2 (first arg -> low half)
__device__ __forceinline__ uint32_t packbf(float lo, float hi) {
    uint32_t r;
    asm("cvt.rn.bf16x2.f32 %0, %1, %2;" : "=r"(r) : "f"(hi), "f"(lo));
    return r;
}
// pack two fp32 -> f16x2 (first arg -> low half)
__device__ __forceinline__ uint32_t packh(float lo, float hi) {
    uint32_t r;
    asm("cvt.rn.f16x2.f32 %0, %1, %2;" : "=r"(r) : "f"(hi), "f"(lo));
    return r;
}
__device__ __forceinline__ float2 bf2f(uint32_t u) {
    __nv_bfloat162 t = *reinterpret_cast<__nv_bfloat162*>(&u);
    return __bfloat1622float2(t);
}
__device__ __forceinline__ float2 h2f(uint32_t u) {
    __half2 t = *reinterpret_cast<__half2*>(&u);
    return __half22float2(t);
}
__device__ __forceinline__ float ex2(float x) {
    float r;
    asm("ex2.approx.ftz.f32 %0, %1;" : "=f"(r) : "f"(x));
    return r;
}
__device__ __forceinline__ void cpa16(uint32_t dst, const void* src) {
    asm volatile("cp.async.cg.shared.global [%0], [%1], 16;" :: "r"(dst), "l"(src));
}
#define CP_COMMIT asm volatile("cp.async.commit_group;")
#define CP_WAIT0  asm volatile("cp.async.wait_group 0;")
#define CP_WAIT1  asm volatile("cp.async.wait_group 1;")

// ---------------------------------------------------------------------------
// Kernel 0: split x and W into bf16 hi/lo.
// ---------------------------------------------------------------------------
__global__ __launch_bounds__(256) void split_xw(
    const float* __restrict__ x, const float* __restrict__ W)
{
    int i4 = (blockIdx.x * 256 + threadIdx.x) * 4;
    const float* src;
    __nv_bfloat16 *dh, *dl;
    int off;
    if (i4 < XN) {
        src = x; dh = g_xh; dl = g_xl; off = i4;
    } else {
        off = i4 - XN;
        if (off >= WN) return;
        src = W; dh = g_wh; dl = g_wl;
    }
    float4 v = *(const float4*)(src + off);
    uint32_t h01 = packbf(v.x, v.y), h23 = packbf(v.z, v.w);
    float2 f01 = bf2f(h01), f23 = bf2f(h23);
    *(uint2*)&dh[off] = make_uint2(h01, h23);
    *(uint2*)&dl[off] = make_uint2(packbf(v.x - f01.x, v.y - f01.y),
                                   packbf(v.z - f23.x, v.w - f23.y));
}

// ---------------------------------------------------------------------------
// Kernel 1: QKV projection via split-bf16 MMA, 3-stage cp.async pipeline.
// Epilogue: Q scaled by log2(e)/sqrt(D) then split-bf16; K split-bf16;
// V -> plain fp16 into g_v16.
// ---------------------------------------------------------------------------
__global__ __launch_bounds__(256) void qkv_gemm_mma(const float* __restrict__ bias)
{
    extern __shared__ __align__(16) unsigned char smg[];
    const int tid = threadIdx.x;
    const int w = tid >> 5, l = tid & 31;
    const int l16 = l & 15;
    const int mw = 32 * (w & 1);
    const int nw = 16 * (w >> 1);
    const int rb = blockIdx.y * 64;
    const int cb = blockIdx.x * 64;

    const int xrow = tid >> 2, xpart = tid & 3;
    const int wrow = tid >> 3, wpart = tid & 7;

    auto stage = [&](int k0, unsigned char* buf) {
        cpa16(sptr(buf + xrow * 80 + xpart * 16),
              g_xh + (size_t)(rb + xrow) * 256 + k0 + xpart * 8);
        cpa16(sptr(buf + 5120 + xrow * 80 + xpart * 16),
              g_xl + (size_t)(rb + xrow) * 256 + k0 + xpart * 8);
        cpa16(sptr(buf + 10240 + wrow * 144 + wpart * 16),
              g_wh + (size_t)(k0 + wrow) * 768 + cb + wpart * 8);
        cpa16(sptr(buf + 14848 + wrow * 144 + wpart * 16),
              g_wl + (size_t)(k0 + wrow) * 768 + cb + wpart * 8);
    };

    float acc[2][2][4] = {};

    stage(0, smg);            CP_COMMIT;
    stage(32, smg + 19456);   CP_COMMIT;

    for (int c = 0; c < 8; c++) {
        if (c < 7) { CP_WAIT1; } else { CP_WAIT0; }
        __syncthreads();
        if (c < 6) {
            stage((c + 2) * 32, smg + ((c + 2) % 3) * 19456);
            CP_COMMIT;
        }
        unsigned char* buf = smg + (c % 3) * 19456;
        const __nv_bfloat16* xh = (const __nv_bfloat16*)(buf);
        const __nv_bfloat16* xl = (const __nv_bfloat16*)(buf + 5120);
        const __nv_bfloat16* wh = (const __nv_bfloat16*)(buf + 10240);
        const __nv_bfloat16* wl = (const __nv_bfloat16*)(buf + 14848);

        #pragma unroll
        for (int ks = 0; ks < 2; ks++) {
            uint32_t ah[2][4], al[2][4];
            #pragma unroll
            for (int mf = 0; mf < 2; mf++) {
                int aoff = (mw + 16 * mf + l16) * 40 + ks * 16 + ((l & 16) >> 1);
                ldmx4(ah[mf], sptr(xh + aoff));
                ldmx4(al[mf], sptr(xl + aoff));
            }
            #pragma unroll
            for (int t = 0; t < 2; t++) {
                int woff = (ks * 16 + l16) * 72 + nw + 8 * t;
                uint32_t bh[2], bl[2];
                ldmx2t(bh, sptr(wh + woff));
                ldmx2t(bl, sptr(wl + woff));
                #pragma unroll
                for (int mf = 0; mf < 2; mf++) {
                    mma_bf16(acc[mf][t], ah[mf], bh[0], bh[1]);
                    mma_bf16(acc[mf][t], al[mf], bh[0], bh[1]);
                    mma_bf16(acc[mf][t], ah[mf], bl[0], bl[1]);
                }
            }
        }
    }

    // Q scale folds 1/sqrt(32) AND log2(e) so attention can use ex2 directly
    const float QSCALE = 0.17677669529663687f * 1.4426950408889634f;

    #pragma unroll
    for (int t = 0; t < 2; t++) {
        int c0 = cb + nw + 8 * t + 2 * (l & 3);
        int s = c0 >> 8, rem = c0 & 255, h = rem >> 5, d = rem & 31;
        float sc = (s == 0) ? QSCALE : 1.0f;
        float b0 = bias[c0], b1 = bias[c0 + 1];
        #pragma unroll
        for (int mf = 0; mf < 2; mf++) {
            #pragma unroll
            for (int rr = 0; rr < 2; rr++) {
                int r = rb + mw + 16 * mf + (l >> 2) + 8 * rr;
                int bq = r >> 10, n = r & 1023;
                float v0 = (acc[mf][t][2 * rr + 0] + b0) * sc;
                float v1 = (acc[mf][t][2 * rr + 1] + b1) * sc;
                if (s == 2) {
                    size_t idxv = ((size_t)(bq * 8 + h) * 1024 + n) * 32 + d;
                    *(uint32_t*)&g_v16[idxv] = packh(v0, v1);
                } else {
                    uint32_t hv = packbf(v0, v1);
                    float2 f = bf2f(hv);
                    uint32_t lv = packbf(v0 - f.x, v1 - f.y);
                    size_t idx = ((size_t)((s * 8 + bq) * 8 + h) * 1024 + n) * 32 + d;
                    *(uint32_t*)&g_hi[idx] = hv;
                    *(uint32_t*)&g_lo[idx] = lv;
                }
            }
        }
    }
}

// ---------------------------------------------------------------------------
// Kernel 2: tensor-core moire attention.
//  - V in plain fp16: PV = Ph@V + Pl@V (2 MMAs)
//  - log2-domain exponents; weights RE-CENTERED by +15 octaves so P sits in
//    fp16 normal range (scale cancels in Oacc/lsum ratio):
//       w' = ex2(fq*(v+kb) + 15) = 2^15 * w
//    masked-q rows: ex2(15) uniform -> cancels; masked-k: 0.
// Stage = {Kh 5120, Kl 5120, Vf 5120} = 15360 B; smem = 8192 + 3*15360 = 54272.
// ---------------------------------------------------------------------------
__global__ __launch_bounds__(256, 2) void moire_attn(
    const float* __restrict__ adj, const unsigned int* __restrict__ mask,
    const float* __restrict__ shifts, const float* __restrict__ widths,
    const float* __restrict__ slw, float* __restrict__ out)
{
    extern __shared__ __align__(16) unsigned char smraw[];

    const int hh = blockIdx.x;
    const int q0 = blockIdx.y * 64;
    const int bb = blockIdx.z;
    const int tid = threadIdx.x;
    const int w   = tid >> 5;
    const int l   = tid & 31;
    const int wm  = w & 3;
    const int wk  = w >> 2;
    const int m0  = 16 * wm;
    const int n0k = 32 * wk;
    const int l16 = l & 15;
    const int qal = m0 + (l >> 2);
    const int qbl = qal + 8;

    const float LOG2E = 1.4426950408889634f;
    const float sh    = shifts[hh];
    const float invw2 = LOG2E / fmaxf(widths[hh], 0.5f);
    const float sl2   = slw[hh] * LOG2E;
    const float LOGEPS2 = -19.931568569324174f;   // log2(1e-6)

    const size_t qbase = ((size_t)((0 * 8 + bb) * 8 + hh)) * 1024 * 32;
    const size_t kbase = ((size_t)((1 * 8 + bb) * 8 + hh)) * 1024 * 32;
    const size_t vbase = ((size_t)(bb * 8 + hh)) * 1024 * 32;   // g_v16

    __nv_bfloat16* Qh = (__nv_bfloat16*)(smraw);
    __nv_bfloat16* Ql = (__nv_bfloat16*)(smraw + 4096);

    const int row = tid >> 2, part = tid & 3;

    auto stageKV = [&](int kb, unsigned char* buf) {
        size_t gk = kbase + (size_t)(kb + row) * 32 + part * 8;
        size_t gv = vbase + (size_t)(kb + row) * 32 + part * 8;
        cpa16(sptr(buf + row * 80 + part * 16),         g_hi + gk);
        cpa16(sptr(buf + 5120 + row * 80 + part * 16),  g_lo + gk);
        cpa16(sptr(buf + 10240 + row * 80 + part * 16), g_v16 + gv);
    };

    // stage Q (plain LDG) + prefetch stages 0,1 of K/V
    {
        size_t gq = qbase + (size_t)(q0 + row) * 32 + part * 8;
        *(uint4*)(Qh + row * 32 + part * 8) = *(const uint4*)(g_hi + gq);
        *(uint4*)(Ql + row * 32 + part * 8) = *(const uint4*)(g_lo + gq);
    }
    stageKV(0, smraw + 8192);            CP_COMMIT;
    stageKV(64, smraw + 8192 + 15360);   CP_COMMIT;

    const float fqa = (mask[(size_t)bb * 1024 + q0 + qal] != 0u) ? 1.0f : 0.0f;
    const float fqb = (mask[(size_t)bb * 1024 + q0 + qbl] != 0u) ? 1.0f : 0.0f;
    __syncthreads();

    uint32_t qfh[2][4], qfl[2][4];
    #pragma unroll
    for (int ks = 0; ks < 2; ks++) {
        int off = (m0 + l16) * 32 + ks * 16 + ((l & 16) >> 1);
        ldmx4(qfh[ks], sptr(Qh + off));
        ldmx4(qfl[ks], sptr(Ql + off));
    }

    // V ldmatrix.x4.trans lane address components
    const int vmi = l >> 3, vr = l & 7;
    const int vrow_off = (vmi & 1) * 8 + vr;     // k within 16
    const int vcol_off = 8 * (vmi >> 1);         // second n8 tile select

    float Oacc[4][4] = {};
    float lsa = 0.0f, lsb = 0.0f;

    for (int it = 0; it < 16; it++) {
        const int kb = it * 64;
        // adj + mask prefetch (regs; overlaps pipeline drain)
        float2 av[2][4];
        uint2  mkp[4];
        {
            const float* ap = adj + ((size_t)(bb * 1024 + q0 + qal)) * 1024
                              + kb + n0k + 2 * (l & 3);
            const unsigned int* mp = mask + (size_t)bb * 1024 + kb + n0k + 2 * (l & 3);
            #pragma unroll
            for (int t = 0; t < 4; t++) {
                av[0][t] = *(const float2*)(ap + 8 * t);
                av[1][t] = *(const float2*)(ap + 8 * 1024 + 8 * t);
                mkp[t]   = *(const uint2*)(mp + 8 * t);
            }
        }
        if (it < 15) { CP_WAIT1; } else { CP_WAIT0; }
        __syncthreads();   // stage `it` visible to all; iter it-1 reads done
        if (it < 14) {
            stageKV(kb + 128, smraw + 8192 + ((it + 2) % 3) * 15360);
            CP_COMMIT;
        }

        unsigned char* buf = smraw + 8192 + (it % 3) * 15360;
        const __nv_bfloat16* Kh = (const __nv_bfloat16*)(buf);
        const __nv_bfloat16* Kl = (const __nv_bfloat16*)(buf + 5120);
        const __half*        Vf = (const __half*)(buf + 10240);

        // ---- QK: 4 n8-tile accumulators; K B-frags via ldmatrix.x4 ----
        float acc[4][4] = {};
        #pragma unroll
        for (int ks = 0; ks < 2; ks++) {
            #pragma unroll
            for (int t2 = 0; t2 < 2; t2++) {
                int koff = (n0k + 16 * t2 + l16) * 40 + ks * 16 + ((l & 16) >> 1);
                uint32_t rh[4], rl[4];
                ldmx4(rh, sptr(Kh + koff));
                ldmx4(rl, sptr(Kl + koff));
                mma_bf16(acc[2 * t2],     qfh[ks], rh[0], rh[2]);
                mma_bf16(acc[2 * t2],     qfl[ks], rh[0], rh[2]);
                mma_bf16(acc[2 * t2],     qfh[ks], rl[0], rl[2]);
                mma_bf16(acc[2 * t2 + 1], qfh[ks], rh[1], rh[3]);
                mma_bf16(acc[2 * t2 + 1], qfl[ks], rh[1], rh[3]);
                mma_bf16(acc[2 * t2 + 1], qfh[ks], rl[1], rl[3]);
            }
        }

        // ---- elementwise (log2-domain): moire + self-loop + mask + ex2 ----
        const bool diag = (kb == q0);
        #pragma unroll
        for (int t = 0; t < 4; t++) {
            int c0 = n0k + 8 * t + 2 * (l & 3);
            // column bias: -12*log2e valid, huge negative if masked
            float kb0 = (mkp[t].x != 0u) ? -17.312340490667560f : -1442712.4f;
            float kb1 = (mkp[t].y != 0u) ? -17.312340490667560f : -1442712.4f;
            float ax = av[0][t].x - sh, ay = av[0][t].y - sh;
            float bx = av[1][t].x - sh, by = av[1][t].y - sh;
            float v00 = acc[t][0] + fmaxf(-ax * ax * invw2, LOGEPS2);
            float v01 = acc[t][1] + fmaxf(-ay * ay * invw2, LOGEPS2);
            float v10 = acc[t][2] + fmaxf(-bx * bx * invw2, LOGEPS2);
            float v11 = acc[t][3] + fmaxf(-by * by * invw2, LOGEPS2);
            if (diag) {
                if (qal == c0)     v00 += sl2;
                if (qal == c0 + 1) v01 += sl2;
                if (qbl == c0)     v10 += sl2;
                if (qbl == c0 + 1) v11 += sl2;
            }
            // +15 octaves re-centers weights into fp16 normal range;
            // the 2^15 scale cancels in Oacc/lsum.
            float w00 = ex2(fqa * (v00 + kb0) + 15.0f);
            float w01 = ex2(fqa * (v01 + kb1) + 15.0f);
            float w10 = ex2(fqb * (v10 + kb0) + 15.0f);
            float w11 = ex2(fqb * (v11 + kb1) + 15.0f);
            lsa += w00 + w01;
            lsb += w10 + w11;
            acc[t][0] = w00; acc[t][1] = w01; acc[t][2] = w10; acc[t][3] = w11;
        }

        // ---- P fragments in fp16 (hi + residual lo) ----
        uint32_t pfh[2][4], pfl[2][4];
        #pragma unroll
        for (int cch = 0; cch < 2; cch++) {
            #pragma unroll
            for (int rr = 0; rr < 2; rr++) {
                const float* a4 = acc[2 * cch + rr];
                uint32_t u0 = packh(a4[0], a4[1]);
                uint32_t u1 = packh(a4[2], a4[3]);
                float2 f0 = h2f(u0), f1 = h2f(u1);
                pfh[cch][rr * 2 + 0] = u0;
                pfh[cch][rr * 2 + 1] = u1;
                pfl[cch][rr * 2 + 0] = packh(a4[0] - f0.x, a4[1] - f0.y);
                pfl[cch][rr * 2 + 1] = packh(a4[2] - f1.x, a4[3] - f1.y);
            }
        }

        // ---- PV: O += Ph@V + Pl@V (fp16); V frags via x4.trans ----
        #pragma unroll
        for (int cch = 0; cch < 2; cch++) {
            #pragma unroll
            for (int tdp = 0; tdp < 2; tdp++) {
                int voff = (n0k + 16 * cch + vrow_off) * 40 + 8 * (2 * tdp) + vcol_off;
                uint32_t rv[4];
                ldmx4t(rv, sptr(Vf + voff));
                mma_f16(Oacc[2 * tdp],     pfh[cch], rv[0], rv[1]);
                mma_f16(Oacc[2 * tdp],     pfl[cch], rv[0], rv[1]);
                mma_f16(Oacc[2 * tdp + 1], pfh[cch], rv[2], rv[3]);
                mma_f16(Oacc[2 * tdp + 1], pfl[cch], rv[2], rv[3]);
            }
        }
    }

    // ---- lsum: zero (overlay on stage area), reduce, accumulate ----
    __syncthreads();
    float* lsum = (float*)(smraw + 8192);
    if (tid < 64) lsum[tid] = 0.0f;
    __syncthreads();
    lsa += __shfl_xor_sync(0xffffffffu, lsa, 1);
    lsa += __shfl_xor_sync(0xffffffffu, lsa, 2);
    lsb += __shfl_xor_sync(0xffffffffu, lsb, 1);
    lsb += __shfl_xor_sync(0xffffffffu, lsb, 2);
    if ((l & 3) == 0) {
        atomicAdd(&lsum[qal], lsa);
        atomicAdd(&lsum[qbl], lsb);
    }

    // ---- combine wk halves via Obuf (overlays Qh/Ql) and write out ----
    float* Obuf = (float*)smraw;  // 64 x 32 floats = 8KB
    if (wk == 1) {
        #pragma unroll
        for (int td = 0; td < 4; td++) {
            int n = 8 * td + 2 * (l & 3);
            *(float2*)&Obuf[qal * 32 + n] = make_float2(Oacc[td][0], Oacc[td][1]);
            *(float2*)&Obuf[qbl * 32 + n] = make_float2(Oacc[td][2], Oacc[td][3]);
        }
    }
    __syncthreads();
    if (wk == 0) {
        float rla = 1.0f / lsum[qal];
        float rlb = 1.0f / lsum[qbl];
        #pragma unroll
        for (int td = 0; td < 4; td++) {
            int n = 8 * td + 2 * (l & 3);
            float2 oa = *(const float2*)&Obuf[qal * 32 + n];
            float2 ob = *(const float2*)&Obuf[qbl * 32 + n];
            oa.x = (oa.x + Oacc[td][0]) * rla;
            oa.y = (oa.y + Oacc[td][1]) * rla;
            ob.x = (ob.x + Oacc[td][2]) * rlb;
            ob.y = (ob.y + Oacc[td][3]) * rlb;
            *(float2*)&out[((size_t)bb * 1024 + q0 + qal) * 256 + hh * 32 + n] = oa;
            *(float2*)&out[((size_t)bb * 1024 + q0 + qbl) * 256 + hh * 32 + n] = ob;
        }
    }
}

// ---------------------------------------------------------------------------
// Launch. Inputs: x, adj, mask, W_qkv, b_qkv, shifts, widths, self_loop_w
// ---------------------------------------------------------------------------
extern "C" void kernel_launch(void* const* d_in, const int* in_sizes, int n_in,
                              void* d_out, int out_size)
{
    const float*        x      = (const float*)d_in[0];
    const float*        adj    = (const float*)d_in[1];
    const unsigned int* mask   = (const unsigned int*)d_in[2];
    const float*        W_qkv  = (const float*)d_in[3];
    const float*        b_qkv  = (const float*)d_in[4];
    const float*        shifts = (const float*)d_in[5];
    const float*        widths = (const float*)d_in[6];
    const float*        slw    = (const float*)d_in[7];
    float*              out    = (float*)d_out;

    static bool attr_done = false;
    if (!attr_done) {
        cudaFuncSetAttribute(qkv_gemm_mma,
            cudaFuncAttributeMaxDynamicSharedMemorySize, 3 * 19456);
        cudaFuncSetAttribute(moire_attn,
            cudaFuncAttributeMaxDynamicSharedMemorySize, 8192 + 3 * 15360);
        attr_done = true;
    }

    split_xw<<<(XN + WN) / 1024, 256>>>(x, W_qkv);
    qkv_gemm_mma<<<dim3(12, 128), 256, 3 * 19456>>>(b_qkv);
    moire_attn<<<dim3(8, 16, 8), 256, 8192 + 3 * 15360>>>(
        adj, mask, shifts, widths, slw, out);
}

// round 15
// speedup vs baseline: 1.4112x; 1.0810x over previous
#include <cuda_runtime.h>
#include <cuda_bf16.h>
#include <cuda_fp16.h>
#include <cstdint>

#define B_ 8
#define N_ 1024
#define H_ 8
#define D_ 32
#define XN (8192 * 256)
#define WN (256 * 768)

// split-bf16 Q/K scratch: [s][b][h][n][d], Q pre-scaled by log2(e)/sqrt(D)
#define QKV_ELEMS (3u * B_ * H_ * N_ * D_)
__device__ __nv_bfloat16 g_hi[QKV_ELEMS];
__device__ __nv_bfloat16 g_lo[QKV_ELEMS];
// V scratch: plain fp16
__device__ __half g_v16[B_ * H_ * N_ * D_];
// split-bf16 GEMM operands
__device__ __nv_bfloat16 g_xh[XN], g_xl[XN];
__device__ __nv_bfloat16 g_wh[WN], g_wl[WN];

// ---------------------------------------------------------------------------
// PTX helpers
// ---------------------------------------------------------------------------
__device__ __forceinline__ uint32_t sptr(const void* p) {
    return (uint32_t)__cvta_generic_to_shared(p);
}
__device__ __forceinline__ void ldmx4(uint32_t* r, uint32_t a) {
    asm volatile("ldmatrix.sync.aligned.m8n8.x4.shared.b16 {%0,%1,%2,%3}, [%4];"
                 : "=r"(r[0]), "=r"(r[1]), "=r"(r[2]), "=r"(r[3]) : "r"(a));
}
__device__ __forceinline__ void ldmx4t(uint32_t* r, uint32_t a) {
    asm volatile("ldmatrix.sync.aligned.m8n8.x4.trans.shared.b16 {%0,%1,%2,%3}, [%4];"
                 : "=r"(r[0]), "=r"(r[1]), "=r"(r[2]), "=r"(r[3]) : "r"(a));
}
__device__ __forceinline__ void ldmx2t(uint32_t* r, uint32_t a) {
    asm volatile("ldmatrix.sync.aligned.m8n8.x2.trans.shared.b16 {%0,%1}, [%2];"
                 : "=r"(r[0]), "=r"(r[1]) : "r"(a));
}
__device__ __forceinline__ void mma_bf16(float* d, const uint32_t* a,
                                         uint32_t b0, uint32_t b1) {
    asm volatile("mma.sync.aligned.m16n8k16.row.col.f32.bf16.bf16.f32 "
                 "{%0,%1,%2,%3}, {%4,%5,%6,%7}, {%8,%9}, {%0,%1,%2,%3};"
                 : "+f"(d[0]), "+f"(d[1]), "+f"(d[2]), "+f"(d[3])
                 : "r"(a[0]), "r"(a[1]), "r"(a[2]), "r"(a[3]), "r"(b0), "r"(b1));
}
__device__ __forceinline__ void mma_f16(float* d, const uint32_t* a,
                                        uint32_t b0, uint32_t b1) {
    asm volatile("mma.sync.aligned.m16n8k16.row.col.f32.f16.f16.f32 "
                 "{%0,%1,%2,%3}, {%4,%5,%6,%7}, {%8,%9}, {%0,%1,%2,%3};"
                 : "+f"(d[0]), "+f"(d[1]), "+f"(d[2]), "+f"(d[3])
                 : "r"(a[0]), "r"(a[1]), "r"(a[2]), "r"(a[3]), "r"(b0), "r"(b1));
}
// pack two fp32 -> bf16x2 (first arg -> low half)
__device__ __forceinline__ uint32_t packbf(float lo, float hi) {
    uint32_t r;
    asm("cvt.rn.bf16x2.f32 %0, %1, %2;" : "=r"(r) : "f"(hi), "f"(lo));
    return r;
}
// pack two fp32 -> f16x2 (first arg -> low half)
__device__ __forceinline__ uint32_t packh(float lo, float hi) {
    uint32_t r;
    asm("cvt.rn.f16x2.f32 %0, %1, %2;" : "=r"(r) : "f"(hi), "f"(lo));
    return r;
}
__device__ __forceinline__ float2 bf2f(uint32_t u) {
    __nv_bfloat162 t = *reinterpret_cast<__nv_bfloat162*>(&u);
    return __bfloat1622float2(t);
}
__device__ __forceinline__ float ex2(float x) {
    float r;
    asm("ex2.approx.ftz.f32 %0, %1;" : "=f"(r) : "f"(x));
    return r;
}
__device__ __forceinline__ void cpa16(uint32_t dst, const void* src) {
    asm volatile("cp.async.cg.shared.global [%0], [%1], 16;" :: "r"(dst), "l"(src));
}
#define CP_COMMIT asm volatile("cp.async.commit_group;")
#define CP_WAIT0  asm volatile("cp.async.wait_group 0;")
#define CP_WAIT1  asm volatile("cp.async.wait_group 1;")

// ---------------------------------------------------------------------------
// Kernel 0: split x and W into bf16 hi/lo.
// ---------------------------------------------------------------------------
__global__ __launch_bounds__(256) void split_xw(
    const float* __restrict__ x, const float* __restrict__ W)
{
    int i4 = (blockIdx.x * 256 + threadIdx.x) * 4;
    const float* src;
    __nv_bfloat16 *dh, *dl;
    int off;
    if (i4 < XN) {
        src = x; dh = g_xh; dl = g_xl; off = i4;
    } else {
        off = i4 - XN;
        if (off >= WN) return;
        src = W; dh = g_wh; dl = g_wl;
    }
    float4 v = *(const float4*)(src + off);
    uint32_t h01 = packbf(v.x, v.y), h23 = packbf(v.z, v.w);
    float2 f01 = bf2f(h01), f23 = bf2f(h23);
    *(uint2*)&dh[off] = make_uint2(h01, h23);
    *(uint2*)&dl[off] = make_uint2(packbf(v.x - f01.x, v.y - f01.y),
                                   packbf(v.z - f23.x, v.w - f23.y));
}

// ---------------------------------------------------------------------------
// Kernel 1: QKV projection via split-bf16 MMA, 3-stage cp.async pipeline.
// Epilogue: Q scaled by log2(e)/sqrt(D) then split-bf16; K split-bf16;
// V -> plain fp16 into g_v16.
// ---------------------------------------------------------------------------
__global__ __launch_bounds__(256) void qkv_gemm_mma(const float* __restrict__ bias)
{
    extern __shared__ __align__(16) unsigned char smg[];
    const int tid = threadIdx.x;
    const int w = tid >> 5, l = tid & 31;
    const int l16 = l & 15;
    const int mw = 32 * (w & 1);
    const int nw = 16 * (w >> 1);
    const int rb = blockIdx.y * 64;
    const int cb = blockIdx.x * 64;

    const int xrow = tid >> 2, xpart = tid & 3;
    const int wrow = tid >> 3, wpart = tid & 7;

    auto stage = [&](int k0, unsigned char* buf) {
        cpa16(sptr(buf + xrow * 80 + xpart * 16),
              g_xh + (size_t)(rb + xrow) * 256 + k0 + xpart * 8);
        cpa16(sptr(buf + 5120 + xrow * 80 + xpart * 16),
              g_xl + (size_t)(rb + xrow) * 256 + k0 + xpart * 8);
        cpa16(sptr(buf + 10240 + wrow * 144 + wpart * 16),
              g_wh + (size_t)(k0 + wrow) * 768 + cb + wpart * 8);
        cpa16(sptr(buf + 14848 + wrow * 144 + wpart * 16),
              g_wl + (size_t)(k0 + wrow) * 768 + cb + wpart * 8);
    };

    float acc[2][2][4] = {};

    stage(0, smg);            CP_COMMIT;
    stage(32, smg + 19456);   CP_COMMIT;

    for (int c = 0; c < 8; c++) {
        if (c < 7) { CP_WAIT1; } else { CP_WAIT0; }
        __syncthreads();
        if (c < 6) {
            stage((c + 2) * 32, smg + ((c + 2) % 3) * 19456);
            CP_COMMIT;
        }
        unsigned char* buf = smg + (c % 3) * 19456;
        const __nv_bfloat16* xh = (const __nv_bfloat16*)(buf);
        const __nv_bfloat16* xl = (const __nv_bfloat16*)(buf + 5120);
        const __nv_bfloat16* wh = (const __nv_bfloat16*)(buf + 10240);
        const __nv_bfloat16* wl = (const __nv_bfloat16*)(buf + 14848);

        #pragma unroll
        for (int ks = 0; ks < 2; ks++) {
            uint32_t ah[2][4], al[2][4];
            #pragma unroll
            for (int mf = 0; mf < 2; mf++) {
                int aoff = (mw + 16 * mf + l16) * 40 + ks * 16 + ((l & 16) >> 1);
                ldmx4(ah[mf], sptr(xh + aoff));
                ldmx4(al[mf], sptr(xl + aoff));
            }
            #pragma unroll
            for (int t = 0; t < 2; t++) {
                int woff = (ks * 16 + l16) * 72 + nw + 8 * t;
                uint32_t bh[2], bl[2];
                ldmx2t(bh, sptr(wh + woff));
                ldmx2t(bl, sptr(wl + woff));
                #pragma unroll
                for (int mf = 0; mf < 2; mf++) {
                    mma_bf16(acc[mf][t], ah[mf], bh[0], bh[1]);
                    mma_bf16(acc[mf][t], al[mf], bh[0], bh[1]);
                    mma_bf16(acc[mf][t], ah[mf], bl[0], bl[1]);
                }
            }
        }
    }

    // Q scale folds 1/sqrt(32) AND log2(e) so attention can use ex2 directly
    const float QSCALE = 0.17677669529663687f * 1.4426950408889634f;

    #pragma unroll
    for (int t = 0; t < 2; t++) {
        int c0 = cb + nw + 8 * t + 2 * (l & 3);
        int s = c0 >> 8, rem = c0 & 255, h = rem >> 5, d = rem & 31;
        float sc = (s == 0) ? QSCALE : 1.0f;
        float b0 = bias[c0], b1 = bias[c0 + 1];
        #pragma unroll
        for (int mf = 0; mf < 2; mf++) {
            #pragma unroll
            for (int rr = 0; rr < 2; rr++) {
                int r = rb + mw + 16 * mf + (l >> 2) + 8 * rr;
                int bq = r >> 10, n = r & 1023;
                float v0 = (acc[mf][t][2 * rr + 0] + b0) * sc;
                float v1 = (acc[mf][t][2 * rr + 1] + b1) * sc;
                if (s == 2) {
                    size_t idxv = ((size_t)(bq * 8 + h) * 1024 + n) * 32 + d;
                    *(uint32_t*)&g_v16[idxv] = packh(v0, v1);
                } else {
                    uint32_t hv = packbf(v0, v1);
                    float2 f = bf2f(hv);
                    uint32_t lv = packbf(v0 - f.x, v1 - f.y);
                    size_t idx = ((size_t)((s * 8 + bq) * 8 + h) * 1024 + n) * 32 + d;
                    *(uint32_t*)&g_hi[idx] = hv;
                    *(uint32_t*)&g_lo[idx] = lv;
                }
            }
        }
    }
}

// ---------------------------------------------------------------------------
// Kernel 2: tensor-core moire attention.
//  - V plain fp16, P plain fp16 (re-centered +15 octaves -> fp16 normal range,
//    rel err 2^-11; scale cancels in Oacc/lsum): PV = P@V, ONE MMA pair.
//  - log2-domain exponents: w' = ex2(fq*(v+kb) + 15)
// Stage = {Kh 5120, Kl 5120, Vf 5120} = 15360 B; smem = 8192 + 3*15360 = 54272.
// ---------------------------------------------------------------------------
__global__ __launch_bounds__(256, 2) void moire_attn(
    const float* __restrict__ adj, const unsigned int* __restrict__ mask,
    const float* __restrict__ shifts, const float* __restrict__ widths,
    const float* __restrict__ slw, float* __restrict__ out)
{
    extern __shared__ __align__(16) unsigned char smraw[];

    const int hh = blockIdx.x;
    const int q0 = blockIdx.y * 64;
    const int bb = blockIdx.z;
    const int tid = threadIdx.x;
    const int w   = tid >> 5;
    const int l   = tid & 31;
    const int wm  = w & 3;
    const int wk  = w >> 2;
    const int m0  = 16 * wm;
    const int n0k = 32 * wk;
    const int l16 = l & 15;
    const int qal = m0 + (l >> 2);
    const int qbl = qal + 8;

    const float LOG2E = 1.4426950408889634f;
    const float sh    = shifts[hh];
    const float invw2 = LOG2E / fmaxf(widths[hh], 0.5f);
    const float sl2   = slw[hh] * LOG2E;
    const float LOGEPS2 = -19.931568569324174f;   // log2(1e-6)

    const size_t qbase = ((size_t)((0 * 8 + bb) * 8 + hh)) * 1024 * 32;
    const size_t kbase = ((size_t)((1 * 8 + bb) * 8 + hh)) * 1024 * 32;
    const size_t vbase = ((size_t)(bb * 8 + hh)) * 1024 * 32;   // g_v16

    __nv_bfloat16* Qh = (__nv_bfloat16*)(smraw);
    __nv_bfloat16* Ql = (__nv_bfloat16*)(smraw + 4096);

    const int row = tid >> 2, part = tid & 3;

    auto stageKV = [&](int kb, unsigned char* buf) {
        size_t gk = kbase + (size_t)(kb + row) * 32 + part * 8;
        size_t gv = vbase + (size_t)(kb + row) * 32 + part * 8;
        cpa16(sptr(buf + row * 80 + part * 16),         g_hi + gk);
        cpa16(sptr(buf + 5120 + row * 80 + part * 16),  g_lo + gk);
        cpa16(sptr(buf + 10240 + row * 80 + part * 16), g_v16 + gv);
    };

    // stage Q (plain LDG) + prefetch stages 0,1 of K/V
    {
        size_t gq = qbase + (size_t)(q0 + row) * 32 + part * 8;
        *(uint4*)(Qh + row * 32 + part * 8) = *(const uint4*)(g_hi + gq);
        *(uint4*)(Ql + row * 32 + part * 8) = *(const uint4*)(g_lo + gq);
    }
    stageKV(0, smraw + 8192);            CP_COMMIT;
    stageKV(64, smraw + 8192 + 15360);   CP_COMMIT;

    const float fqa = (mask[(size_t)bb * 1024 + q0 + qal] != 0u) ? 1.0f : 0.0f;
    const float fqb = (mask[(size_t)bb * 1024 + q0 + qbl] != 0u) ? 1.0f : 0.0f;
    __syncthreads();

    uint32_t qfh[2][4], qfl[2][4];
    #pragma unroll
    for (int ks = 0; ks < 2; ks++) {
        int off = (m0 + l16) * 32 + ks * 16 + ((l & 16) >> 1);
        ldmx4(qfh[ks], sptr(Qh + off));
        ldmx4(qfl[ks], sptr(Ql + off));
    }

    // V ldmatrix.x4.trans lane address components
    const int vmi = l >> 3, vr = l & 7;
    const int vrow_off = (vmi & 1) * 8 + vr;     // k within 16
    const int vcol_off = 8 * (vmi >> 1);         // second n8 tile select

    float Oacc[4][4] = {};
    float lsa = 0.0f, lsb = 0.0f;

    for (int it = 0; it < 16; it++) {
        const int kb = it * 64;
        // adj + mask prefetch (regs; overlaps pipeline drain)
        float2 av[2][4];
        uint2  mkp[4];
        {
            const float* ap = adj + ((size_t)(bb * 1024 + q0 + qal)) * 1024
                              + kb + n0k + 2 * (l & 3);
            const unsigned int* mp = mask + (size_t)bb * 1024 + kb + n0k + 2 * (l & 3);
            #pragma unroll
            for (int t = 0; t < 4; t++) {
                av[0][t] = *(const float2*)(ap + 8 * t);
                av[1][t] = *(const float2*)(ap + 8 * 1024 + 8 * t);
                mkp[t]   = *(const uint2*)(mp + 8 * t);
            }
        }
        if (it < 15) { CP_WAIT1; } else { CP_WAIT0; }
        __syncthreads();   // stage `it` visible to all; iter it-1 reads done
        if (it < 14) {
            stageKV(kb + 128, smraw + 8192 + ((it + 2) % 3) * 15360);
            CP_COMMIT;
        }

        unsigned char* buf = smraw + 8192 + (it % 3) * 15360;
        const __nv_bfloat16* Kh = (const __nv_bfloat16*)(buf);
        const __nv_bfloat16* Kl = (const __nv_bfloat16*)(buf + 5120);
        const __half*        Vf = (const __half*)(buf + 10240);

        // ---- QK: 4 n8-tile accumulators; K B-frags via ldmatrix.x4 ----
        float acc[4][4] = {};
        #pragma unroll
        for (int ks = 0; ks < 2; ks++) {
            #pragma unroll
            for (int t2 = 0; t2 < 2; t2++) {
                int koff = (n0k + 16 * t2 + l16) * 40 + ks * 16 + ((l & 16) >> 1);
                uint32_t rh[4], rl[4];
                ldmx4(rh, sptr(Kh + koff));
                ldmx4(rl, sptr(Kl + koff));
                mma_bf16(acc[2 * t2],     qfh[ks], rh[0], rh[2]);
                mma_bf16(acc[2 * t2],     qfl[ks], rh[0], rh[2]);
                mma_bf16(acc[2 * t2],     qfh[ks], rl[0], rl[2]);
                mma_bf16(acc[2 * t2 + 1], qfh[ks], rh[1], rh[3]);
                mma_bf16(acc[2 * t2 + 1], qfl[ks], rh[1], rh[3]);
                mma_bf16(acc[2 * t2 + 1], qfh[ks], rl[1], rl[3]);
            }
        }

        // ---- elementwise (log2-domain): moire + self-loop + mask + ex2 ----
        const bool diag = (kb == q0);
        #pragma unroll
        for (int t = 0; t < 4; t++) {
            int c0 = n0k + 8 * t + 2 * (l & 3);
            // column bias: -12*log2e valid, huge negative if masked
            float kb0 = (mkp[t].x != 0u) ? -17.312340490667560f : -1442712.4f;
            float kb1 = (mkp[t].y != 0u) ? -17.312340490667560f : -1442712.4f;
            float ax = av[0][t].x - sh, ay = av[0][t].y - sh;
            float bx = av[1][t].x - sh, by = av[1][t].y - sh;
            float v00 = acc[t][0] + fmaxf(-ax * ax * invw2, LOGEPS2);
            float v01 = acc[t][1] + fmaxf(-ay * ay * invw2, LOGEPS2);
            float v10 = acc[t][2] + fmaxf(-bx * bx * invw2, LOGEPS2);
            float v11 = acc[t][3] + fmaxf(-by * by * invw2, LOGEPS2);
            if (diag) {
                if (qal == c0)     v00 += sl2;
                if (qal == c0 + 1) v01 += sl2;
                if (qbl == c0)     v10 += sl2;
                if (qbl == c0 + 1) v11 += sl2;
            }
            // +15 octaves re-centers weights into fp16 normal range;
            // the 2^15 scale cancels in Oacc/lsum.
            float w00 = ex2(fqa * (v00 + kb0) + 15.0f);
            float w01 = ex2(fqa * (v01 + kb1) + 15.0f);
            float w10 = ex2(fqb * (v10 + kb0) + 15.0f);
            float w11 = ex2(fqb * (v11 + kb1) + 15.0f);
            lsa += w00 + w01;
            lsb += w10 + w11;
            acc[t][0] = w00; acc[t][1] = w01; acc[t][2] = w10; acc[t][3] = w11;
        }

        // ---- P fragments: plain fp16 (re-centered; rel err 2^-11) ----
        uint32_t pfh[2][4];
        #pragma unroll
        for (int cch = 0; cch < 2; cch++) {
            #pragma unroll
            for (int rr = 0; rr < 2; rr++) {
                const float* a4 = acc[2 * cch + rr];
                pfh[cch][rr * 2 + 0] = packh(a4[0], a4[1]);
                pfh[cch][rr * 2 + 1] = packh(a4[2], a4[3]);
            }
        }

        // ---- PV: O += P@V (fp16); V frags via x4.trans ----
        #pragma unroll
        for (int cch = 0; cch < 2; cch++) {
            #pragma unroll
            for (int tdp = 0; tdp < 2; tdp++) {
                int voff = (n0k + 16 * cch + vrow_off) * 40 + 8 * (2 * tdp) + vcol_off;
                uint32_t rv[4];
                ldmx4t(rv, sptr(Vf + voff));
                mma_f16(Oacc[2 * tdp],     pfh[cch], rv[0], rv[1]);
                mma_f16(Oacc[2 * tdp + 1], pfh[cch], rv[2], rv[3]);
            }
        }
    }

    // ---- lsum: zero (overlay on stage area), reduce, accumulate ----
    __syncthreads();
    float* lsum = (float*)(smraw + 8192);
    if (tid < 64) lsum[tid] = 0.0f;
    __syncthreads();
    lsa += __shfl_xor_sync(0xffffffffu, lsa, 1);
    lsa += __shfl_xor_sync(0xffffffffu, lsa, 2);
    lsb += __shfl_xor_sync(0xffffffffu, lsb, 1);
    lsb += __shfl_xor_sync(0xffffffffu, lsb, 2);
    if ((l & 3) == 0) {
        atomicAdd(&lsum[qal], lsa);
        atomicAdd(&lsum[qbl], lsb);
    }

    // ---- combine wk halves via Obuf (overlays Qh/Ql) and write out ----
    float* Obuf = (float*)smraw;  // 64 x 32 floats = 8KB
    if (wk == 1) {
        #pragma unroll
        for (int td = 0; td < 4; td++) {
            int n = 8 * td + 2 * (l & 3);
            *(float2*)&Obuf[qal * 32 + n] = make_float2(Oacc[td][0], Oacc[td][1]);
            *(float2*)&Obuf[qbl * 32 + n] = make_float2(Oacc[td][2], Oacc[td][3]);
        }
    }
    __syncthreads();
    if (wk == 0) {
        float rla = 1.0f / lsum[qal];
        float rlb = 1.0f / lsum[qbl];
        #pragma unroll
        for (int td = 0; td < 4; td++) {
            int n = 8 * td + 2 * (l & 3);
            float2 oa = *(const float2*)&Obuf[qal * 32 + n];
            float2 ob = *(const float2*)&Obuf[qbl * 32 + n];
            oa.x = (oa.x + Oacc[td][0]) * rla;
            oa.y = (oa.y + Oacc[td][1]) * rla;
            ob.x = (ob.x + Oacc[td][2]) * rlb;
            ob.y = (ob.y + Oacc[td][3]) * rlb;
            *(float2*)&out[((size_t)bb * 1024 + q0 + qal) * 256 + hh * 32 + n] = oa;
            *(float2*)&out[((size_t)bb * 1024 + q0 + qbl) * 256 + hh * 32 + n] = ob;
        }
    }
}

// ---------------------------------------------------------------------------
// Launch. Inputs: x, adj, mask, W_qkv, b_qkv, shifts, widths, self_loop_w
// ---------------------------------------------------------------------------
extern "C" void kernel_launch(void* const* d_in, const int* in_sizes, int n_in,
                              void* d_out, int out_size)
{
    const float*        x      = (const float*)d_in[0];
    const float*        adj    = (const float*)d_in[1];
    const unsigned int* mask   = (const unsigned int*)d_in[2];
    const float*        W_qkv  = (const float*)d_in[3];
    const float*        b_qkv  = (const float*)d_in[4];
    const float*        shifts = (const float*)d_in[5];
    const float*        widths = (const float*)d_in[6];
    const float*        slw    = (const float*)d_in[7];
    float*              out    = (float*)d_out;

    static bool attr_done = false;
    if (!attr_done) {
        cudaFuncSetAttribute(qkv_gemm_mma,
            cudaFuncAttributeMaxDynamicSharedMemorySize, 3 * 19456);
        cudaFuncSetAttribute(moire_attn,
            cudaFuncAttributeMaxDynamicSharedMemorySize, 8192 + 3 * 15360);
        attr_done = true;
    }

    split_xw<<<(XN + WN) / 1024, 256>>>(x, W_qkv);
    qkv_gemm_mma<<<dim3(12, 128), 256, 3 * 19456>>>(b_qkv);
    moire_attn<<<dim3(8, 16, 8), 256, 8192 + 3 * 15360>>>(
        adj, mask, shifts, widths, slw, out);
}

// round 16
// speedup vs baseline: 1.5587x; 1.1045x over previous
#include <cuda_runtime.h>
#include <cuda_bf16.h>
#include <cuda_fp16.h>
#include <cstdint>

#define B_ 8
#define N_ 1024
#define H_ 8
#define D_ 32
#define XN (8192 * 256)
#define WN (256 * 768)
#define NHD (B_ * H_ * N_ * D_)

// Q: split fp16 (hi + residual), pre-scaled by log2(e)/sqrt(D)
__device__ __half g_qh[NHD], g_ql[NHD];
// K, V: plain fp16 (rel err 2^-11; error budget per round-15 analysis)
__device__ __half g_k16[NHD], g_v16[NHD];
// split-bf16 GEMM operands
__device__ __nv_bfloat16 g_xh[XN], g_xl[XN];
__device__ __nv_bfloat16 g_wh[WN], g_wl[WN];

// ---------------------------------------------------------------------------
// PTX helpers
// ---------------------------------------------------------------------------
__device__ __forceinline__ uint32_t sptr(const void* p) {
    return (uint32_t)__cvta_generic_to_shared(p);
}
__device__ __forceinline__ void ldmx4(uint32_t* r, uint32_t a) {
    asm volatile("ldmatrix.sync.aligned.m8n8.x4.shared.b16 {%0,%1,%2,%3}, [%4];"
                 : "=r"(r[0]), "=r"(r[1]), "=r"(r[2]), "=r"(r[3]) : "r"(a));
}
__device__ __forceinline__ void ldmx4t(uint32_t* r, uint32_t a) {
    asm volatile("ldmatrix.sync.aligned.m8n8.x4.trans.shared.b16 {%0,%1,%2,%3}, [%4];"
                 : "=r"(r[0]), "=r"(r[1]), "=r"(r[2]), "=r"(r[3]) : "r"(a));
}
__device__ __forceinline__ void ldmx2t(uint32_t* r, uint32_t a) {
    asm volatile("ldmatrix.sync.aligned.m8n8.x2.trans.shared.b16 {%0,%1}, [%2];"
                 : "=r"(r[0]), "=r"(r[1]) : "r"(a));
}
__device__ __forceinline__ void mma_bf16(float* d, const uint32_t* a,
                                         uint32_t b0, uint32_t b1) {
    asm volatile("mma.sync.aligned.m16n8k16.row.col.f32.bf16.bf16.f32 "
                 "{%0,%1,%2,%3}, {%4,%5,%6,%7}, {%8,%9}, {%0,%1,%2,%3};"
                 : "+f"(d[0]), "+f"(d[1]), "+f"(d[2]), "+f"(d[3])
                 : "r"(a[0]), "r"(a[1]), "r"(a[2]), "r"(a[3]), "r"(b0), "r"(b1));
}
__device__ __forceinline__ void mma_f16(float* d, const uint32_t* a,
                                        uint32_t b0, uint32_t b1) {
    asm volatile("mma.sync.aligned.m16n8k16.row.col.f32.f16.f16.f32 "
                 "{%0,%1,%2,%3}, {%4,%5,%6,%7}, {%8,%9}, {%0,%1,%2,%3};"
                 : "+f"(d[0]), "+f"(d[1]), "+f"(d[2]), "+f"(d[3])
                 : "r"(a[0]), "r"(a[1]), "r"(a[2]), "r"(a[3]), "r"(b0), "r"(b1));
}
// pack two fp32 -> bf16x2 (first arg -> low half)
__device__ __forceinline__ uint32_t packbf(float lo, float hi) {
    uint32_t r;
    asm("cvt.rn.bf16x2.f32 %0, %1, %2;" : "=r"(r) : "f"(hi), "f"(lo));
    return r;
}
// pack two fp32 -> f16x2 (first arg -> low half)
__device__ __forceinline__ uint32_t packh(float lo, float hi) {
    uint32_t r;
    asm("cvt.rn.f16x2.f32 %0, %1, %2;" : "=r"(r) : "f"(hi), "f"(lo));
    return r;
}
__device__ __forceinline__ float2 bf2f(uint32_t u) {
    __nv_bfloat162 t = *reinterpret_cast<__nv_bfloat162*>(&u);
    return __bfloat1622float2(t);
}
__device__ __forceinline__ float2 h2f(uint32_t u) {
    __half2 t = *reinterpret_cast<__half2*>(&u);
    return __half22float2(t);
}
__device__ __forceinline__ float ex2(float x) {
    float r;
    asm("ex2.approx.ftz.f32 %0, %1;" : "=f"(r) : "f"(x));
    return r;
}
__device__ __forceinline__ void cpa16(uint32_t dst, const void* src) {
    asm volatile("cp.async.cg.shared.global [%0], [%1], 16;" :: "r"(dst), "l"(src));
}
#define CP_COMMIT asm volatile("cp.async.commit_group;")
#define CP_WAIT0  asm volatile("cp.async.wait_group 0;")
#define CP_WAIT1  asm volatile("cp.async.wait_group 1;")

// ---------------------------------------------------------------------------
// Kernel 0: split x and W into bf16 hi/lo.
// ---------------------------------------------------------------------------
__global__ __launch_bounds__(256) void split_xw(
    const float* __restrict__ x, const float* __restrict__ W)
{
    int i4 = (blockIdx.x * 256 + threadIdx.x) * 4;
    const float* src;
    __nv_bfloat16 *dh, *dl;
    int off;
    if (i4 < XN) {
        src = x; dh = g_xh; dl = g_xl; off = i4;
    } else {
        off = i4 - XN;
        if (off >= WN) return;
        src = W; dh = g_wh; dl = g_wl;
    }
    float4 v = *(const float4*)(src + off);
    uint32_t h01 = packbf(v.x, v.y), h23 = packbf(v.z, v.w);
    float2 f01 = bf2f(h01), f23 = bf2f(h23);
    *(uint2*)&dh[off] = make_uint2(h01, h23);
    *(uint2*)&dl[off] = make_uint2(packbf(v.x - f01.x, v.y - f01.y),
                                   packbf(v.z - f23.x, v.w - f23.y));
}

// ---------------------------------------------------------------------------
// Kernel 1: QKV projection via split-bf16 MMA, 3-stage cp.async pipeline.
// Epilogue: Q -> split fp16 (scaled by log2(e)/sqrt(D)); K, V -> plain fp16.
// ---------------------------------------------------------------------------
__global__ __launch_bounds__(256) void qkv_gemm_mma(const float* __restrict__ bias)
{
    extern __shared__ __align__(16) unsigned char smg[];
    const int tid = threadIdx.x;
    const int w = tid >> 5, l = tid & 31;
    const int l16 = l & 15;
    const int mw = 32 * (w & 1);
    const int nw = 16 * (w >> 1);
    const int rb = blockIdx.y * 64;
    const int cb = blockIdx.x * 64;

    const int xrow = tid >> 2, xpart = tid & 3;
    const int wrow = tid >> 3, wpart = tid & 7;

    auto stage = [&](int k0, unsigned char* buf) {
        cpa16(sptr(buf + xrow * 80 + xpart * 16),
              g_xh + (size_t)(rb + xrow) * 256 + k0 + xpart * 8);
        cpa16(sptr(buf + 5120 + xrow * 80 + xpart * 16),
              g_xl + (size_t)(rb + xrow) * 256 + k0 + xpart * 8);
        cpa16(sptr(buf + 10240 + wrow * 144 + wpart * 16),
              g_wh + (size_t)(k0 + wrow) * 768 + cb + wpart * 8);
        cpa16(sptr(buf + 14848 + wrow * 144 + wpart * 16),
              g_wl + (size_t)(k0 + wrow) * 768 + cb + wpart * 8);
    };

    float acc[2][2][4] = {};

    stage(0, smg);            CP_COMMIT;
    stage(32, smg + 19456);   CP_COMMIT;

    for (int c = 0; c < 8; c++) {
        if (c < 7) { CP_WAIT1; } else { CP_WAIT0; }
        __syncthreads();
        if (c < 6) {
            stage((c + 2) * 32, smg + ((c + 2) % 3) * 19456);
            CP_COMMIT;
        }
        unsigned char* buf = smg + (c % 3) * 19456;
        const __nv_bfloat16* xh = (const __nv_bfloat16*)(buf);
        const __nv_bfloat16* xl = (const __nv_bfloat16*)(buf + 5120);
        const __nv_bfloat16* wh = (const __nv_bfloat16*)(buf + 10240);
        const __nv_bfloat16* wl = (const __nv_bfloat16*)(buf + 14848);

        #pragma unroll
        for (int ks = 0; ks < 2; ks++) {
            uint32_t ah[2][4], al[2][4];
            #pragma unroll
            for (int mf = 0; mf < 2; mf++) {
                int aoff = (mw + 16 * mf + l16) * 40 + ks * 16 + ((l & 16) >> 1);
                ldmx4(ah[mf], sptr(xh + aoff));
                ldmx4(al[mf], sptr(xl + aoff));
            }
            #pragma unroll
            for (int t = 0; t < 2; t++) {
                int woff = (ks * 16 + l16) * 72 + nw + 8 * t;
                uint32_t bh[2], bl[2];
                ldmx2t(bh, sptr(wh + woff));
                ldmx2t(bl, sptr(wl + woff));
                #pragma unroll
                for (int mf = 0; mf < 2; mf++) {
                    mma_bf16(acc[mf][t], ah[mf], bh[0], bh[1]);
                    mma_bf16(acc[mf][t], al[mf], bh[0], bh[1]);
                    mma_bf16(acc[mf][t], ah[mf], bl[0], bl[1]);
                }
            }
        }
    }

    // Q scale folds 1/sqrt(32) AND log2(e) so attention can use ex2 directly
    const float QSCALE = 0.17677669529663687f * 1.4426950408889634f;

    #pragma unroll
    for (int t = 0; t < 2; t++) {
        int c0 = cb + nw + 8 * t + 2 * (l & 3);
        int s = c0 >> 8, rem = c0 & 255, h = rem >> 5, d = rem & 31;
        float sc = (s == 0) ? QSCALE : 1.0f;
        float b0 = bias[c0], b1 = bias[c0 + 1];
        #pragma unroll
        for (int mf = 0; mf < 2; mf++) {
            #pragma unroll
            for (int rr = 0; rr < 2; rr++) {
                int r = rb + mw + 16 * mf + (l >> 2) + 8 * rr;
                int bq = r >> 10, n = r & 1023;
                float v0 = (acc[mf][t][2 * rr + 0] + b0) * sc;
                float v1 = (acc[mf][t][2 * rr + 1] + b1) * sc;
                size_t idx = ((size_t)(bq * 8 + h) * 1024 + n) * 32 + d;
                if (s == 0) {
                    uint32_t hv = packh(v0, v1);
                    float2 f = h2f(hv);
                    *(uint32_t*)&g_qh[idx] = hv;
                    *(uint32_t*)&g_ql[idx] = packh(v0 - f.x, v1 - f.y);
                } else if (s == 1) {
                    *(uint32_t*)&g_k16[idx] = packh(v0, v1);
                } else {
                    *(uint32_t*)&g_v16[idx] = packh(v0, v1);
                }
            }
        }
    }
}

// ---------------------------------------------------------------------------
// Kernel 2: tensor-core moire attention, all-fp16 operands:
//  - QK: (Qh + Ql) @ K, K plain fp16 -> 2 MMAs per tile pair (16/iter)
//  - PV: P plain fp16 (re-centered +15 octaves) @ V fp16 -> 8 MMAs/iter
// Stage = {Kf 5120, Vf 5120} = 10240 B; smem = 8192 + 3*10240 = 38912.
// ---------------------------------------------------------------------------
__global__ __launch_bounds__(256, 2) void moire_attn(
    const float* __restrict__ adj, const unsigned int* __restrict__ mask,
    const float* __restrict__ shifts, const float* __restrict__ widths,
    const float* __restrict__ slw, float* __restrict__ out)
{
    extern __shared__ __align__(16) unsigned char smraw[];

    const int hh = blockIdx.x;
    const int q0 = blockIdx.y * 64;
    const int bb = blockIdx.z;
    const int tid = threadIdx.x;
    const int w   = tid >> 5;
    const int l   = tid & 31;
    const int wm  = w & 3;
    const int wk  = w >> 2;
    const int m0  = 16 * wm;
    const int n0k = 32 * wk;
    const int l16 = l & 15;
    const int qal = m0 + (l >> 2);
    const int qbl = qal + 8;

    const float LOG2E = 1.4426950408889634f;
    const float sh    = shifts[hh];
    const float invw2 = LOG2E / fmaxf(widths[hh], 0.5f);
    const float sl2   = slw[hh] * LOG2E;
    const float LOGEPS2 = -19.931568569324174f;   // log2(1e-6)

    const size_t hbase = ((size_t)(bb * 8 + hh)) * 1024 * 32;

    __half* Qh = (__half*)(smraw);
    __half* Ql = (__half*)(smraw + 4096);

    const int row = tid >> 2, part = tid & 3;

    auto stageKV = [&](int kb, unsigned char* buf) {
        size_t g = hbase + (size_t)(kb + row) * 32 + part * 8;
        cpa16(sptr(buf + row * 80 + part * 16),        g_k16 + g);
        cpa16(sptr(buf + 5120 + row * 80 + part * 16), g_v16 + g);
    };

    // stage Q (plain LDG) + prefetch stages 0,1 of K/V
    {
        size_t gq = hbase + (size_t)(q0 + row) * 32 + part * 8;
        *(uint4*)(Qh + row * 32 + part * 8) = *(const uint4*)(g_qh + gq);
        *(uint4*)(Ql + row * 32 + part * 8) = *(const uint4*)(g_ql + gq);
    }
    stageKV(0, smraw + 8192);            CP_COMMIT;
    stageKV(64, smraw + 8192 + 10240);   CP_COMMIT;

    const float fqa = (mask[(size_t)bb * 1024 + q0 + qal] != 0u) ? 1.0f : 0.0f;
    const float fqb = (mask[(size_t)bb * 1024 + q0 + qbl] != 0u) ? 1.0f : 0.0f;
    __syncthreads();

    uint32_t qfh[2][4], qfl[2][4];
    #pragma unroll
    for (int ks = 0; ks < 2; ks++) {
        int off = (m0 + l16) * 32 + ks * 16 + ((l & 16) >> 1);
        ldmx4(qfh[ks], sptr(Qh + off));
        ldmx4(qfl[ks], sptr(Ql + off));
    }

    // V ldmatrix.x4.trans lane address components
    const int vmi = l >> 3, vr = l & 7;
    const int vrow_off = (vmi & 1) * 8 + vr;     // k within 16
    const int vcol_off = 8 * (vmi >> 1);         // second n8 tile select

    float Oacc[4][4] = {};
    float lsa = 0.0f, lsb = 0.0f;

    for (int it = 0; it < 16; it++) {
        const int kb = it * 64;
        // adj + mask prefetch (regs; overlaps pipeline drain)
        float2 av[2][4];
        uint2  mkp[4];
        {
            const float* ap = adj + ((size_t)(bb * 1024 + q0 + qal)) * 1024
                              + kb + n0k + 2 * (l & 3);
            const unsigned int* mp = mask + (size_t)bb * 1024 + kb + n0k + 2 * (l & 3);
            #pragma unroll
            for (int t = 0; t < 4; t++) {
                av[0][t] = *(const float2*)(ap + 8 * t);
                av[1][t] = *(const float2*)(ap + 8 * 1024 + 8 * t);
                mkp[t]   = *(const uint2*)(mp + 8 * t);
            }
        }
        if (it < 15) { CP_WAIT1; } else { CP_WAIT0; }
        __syncthreads();   // stage `it` visible to all; iter it-1 reads done
        if (it < 14) {
            stageKV(kb + 128, smraw + 8192 + ((it + 2) % 3) * 10240);
            CP_COMMIT;
        }

        unsigned char* buf = smraw + 8192 + (it % 3) * 10240;
        const __half* Kf = (const __half*)(buf);
        const __half* Vf = (const __half*)(buf + 5120);

        // ---- QK: 4 n8-tile accumulators; (Qh + Ql) @ K, K frags via x4 ----
        float acc[4][4] = {};
        #pragma unroll
        for (int ks = 0; ks < 2; ks++) {
            #pragma unroll
            for (int t2 = 0; t2 < 2; t2++) {
                int koff = (n0k + 16 * t2 + l16) * 40 + ks * 16 + ((l & 16) >> 1);
                uint32_t rh[4];
                ldmx4(rh, sptr(Kf + koff));
                mma_f16(acc[2 * t2],     qfh[ks], rh[0], rh[2]);
                mma_f16(acc[2 * t2],     qfl[ks], rh[0], rh[2]);
                mma_f16(acc[2 * t2 + 1], qfh[ks], rh[1], rh[3]);
                mma_f16(acc[2 * t2 + 1], qfl[ks], rh[1], rh[3]);
            }
        }

        // ---- elementwise (log2-domain): moire + self-loop + mask + ex2 ----
        const bool diag = (kb == q0);
        #pragma unroll
        for (int t = 0; t < 4; t++) {
            int c0 = n0k + 8 * t + 2 * (l & 3);
            float kb0 = (mkp[t].x != 0u) ? -17.312340490667560f : -1442712.4f;
            float kb1 = (mkp[t].y != 0u) ? -17.312340490667560f : -1442712.4f;
            float ax = av[0][t].x - sh, ay = av[0][t].y - sh;
            float bx = av[1][t].x - sh, by = av[1][t].y - sh;
            float v00 = acc[t][0] + fmaxf(-ax * ax * invw2, LOGEPS2);
            float v01 = acc[t][1] + fmaxf(-ay * ay * invw2, LOGEPS2);
            float v10 = acc[t][2] + fmaxf(-bx * bx * invw2, LOGEPS2);
            float v11 = acc[t][3] + fmaxf(-by * by * invw2, LOGEPS2);
            if (diag) {
                if (qal == c0)     v00 += sl2;
                if (qal == c0 + 1) v01 += sl2;
                if (qbl == c0)     v10 += sl2;
                if (qbl == c0 + 1) v11 += sl2;
            }
            // +15 octaves re-centers weights into fp16 normal range;
            // the 2^15 scale cancels in Oacc/lsum.
            float w00 = ex2(fqa * (v00 + kb0) + 15.0f);
            float w01 = ex2(fqa * (v01 + kb1) + 15.0f);
            float w10 = ex2(fqb * (v10 + kb0) + 15.0f);
            float w11 = ex2(fqb * (v11 + kb1) + 15.0f);
            lsa += w00 + w01;
            lsb += w10 + w11;
            acc[t][0] = w00; acc[t][1] = w01; acc[t][2] = w10; acc[t][3] = w11;
        }

        // ---- P fragments: plain fp16 (re-centered; rel err 2^-11) ----
        uint32_t pfh[2][4];
        #pragma unroll
        for (int cch = 0; cch < 2; cch++) {
            #pragma unroll
            for (int rr = 0; rr < 2; rr++) {
                const float* a4 = acc[2 * cch + rr];
                pfh[cch][rr * 2 + 0] = packh(a4[0], a4[1]);
                pfh[cch][rr * 2 + 1] = packh(a4[2], a4[3]);
            }
        }

        // ---- PV: O += P@V (fp16); V frags via x4.trans ----
        #pragma unroll
        for (int cch = 0; cch < 2; cch++) {
            #pragma unroll
            for (int tdp = 0; tdp < 2; tdp++) {
                int voff = (n0k + 16 * cch + vrow_off) * 40 + 8 * (2 * tdp) + vcol_off;
                uint32_t rv[4];
                ldmx4t(rv, sptr(Vf + voff));
                mma_f16(Oacc[2 * tdp],     pfh[cch], rv[0], rv[1]);
                mma_f16(Oacc[2 * tdp + 1], pfh[cch], rv[2], rv[3]);
            }
        }
    }

    // ---- lsum: zero (overlay on stage area), reduce, accumulate ----
    __syncthreads();
    float* lsum = (float*)(smraw + 8192);
    if (tid < 64) lsum[tid] = 0.0f;
    __syncthreads();
    lsa += __shfl_xor_sync(0xffffffffu, lsa, 1);
    lsa += __shfl_xor_sync(0xffffffffu, lsa, 2);
    lsb += __shfl_xor_sync(0xffffffffu, lsb, 1);
    lsb += __shfl_xor_sync(0xffffffffu, lsb, 2);
    if ((l & 3) == 0) {
        atomicAdd(&lsum[qal], lsa);
        atomicAdd(&lsum[qbl], lsb);
    }

    // ---- combine wk halves via Obuf (overlays Qh/Ql) and write out ----
    float* Obuf = (float*)smraw;  // 64 x 32 floats = 8KB
    if (wk == 1) {
        #pragma unroll
        for (int td = 0; td < 4; td++) {
            int n = 8 * td + 2 * (l & 3);
            *(float2*)&Obuf[qal * 32 + n] = make_float2(Oacc[td][0], Oacc[td][1]);
            *(float2*)&Obuf[qbl * 32 + n] = make_float2(Oacc[td][2], Oacc[td][3]);
        }
    }
    __syncthreads();
    if (wk == 0) {
        float rla = 1.0f / lsum[qal];
        float rlb = 1.0f / lsum[qbl];
        #pragma unroll
        for (int td = 0; td < 4; td++) {
            int n = 8 * td + 2 * (l & 3);
            float2 oa = *(const float2*)&Obuf[qal * 32 + n];
            float2 ob = *(const float2*)&Obuf[qbl * 32 + n];
            oa.x = (oa.x + Oacc[td][0]) * rla;
            oa.y = (oa.y + Oacc[td][1]) * rla;
            ob.x = (ob.x + Oacc[td][2]) * rlb;
            ob.y = (ob.y + Oacc[td][3]) * rlb;
            *(float2*)&out[((size_t)bb * 1024 + q0 + qal) * 256 + hh * 32 + n] = oa;
            *(float2*)&out[((size_t)bb * 1024 + q0 + qbl) * 256 + hh * 32 + n] = ob;
        }
    }
}

// ---------------------------------------------------------------------------
// Launch. Inputs: x, adj, mask, W_qkv, b_qkv, shifts, widths, self_loop_w
// ---------------------------------------------------------------------------
extern "C" void kernel_launch(void* const* d_in, const int* in_sizes, int n_in,
                              void* d_out, int out_size)
{
    const float*        x      = (const float*)d_in[0];
    const float*        adj    = (const float*)d_in[1];
    const unsigned int* mask   = (const unsigned int*)d_in[2];
    const float*        W_qkv  = (const float*)d_in[3];
    const float*        b_qkv  = (const float*)d_in[4];
    const float*        shifts = (const float*)d_in[5];
    const float*        widths = (const float*)d_in[6];
    const float*        slw    = (const float*)d_in[7];
    float*              out    = (float*)d_out;

    static bool attr_done = false;
    if (!attr_done) {
        cudaFuncSetAttribute(qkv_gemm_mma,
            cudaFuncAttributeMaxDynamicSharedMemorySize, 3 * 19456);
        cudaFuncSetAttribute(moire_attn,
            cudaFuncAttributeMaxDynamicSharedMemorySize, 8192 + 3 * 10240);
        attr_done = true;
    }

    split_xw<<<(XN + WN) / 1024, 256>>>(x, W_qkv);
    qkv_gemm_mma<<<dim3(12, 128), 256, 3 * 19456>>>(b_qkv);
    moire_attn<<<dim3(8, 16, 8), 256, 8192 + 3 * 10240>>>(
        adj, mask, shifts, widths, slw, out);
}

// round 17
// speedup vs baseline: 1.9294x; 1.2378x over previous
#include <cuda_runtime.h>
#include <cuda_bf16.h>
#include <cuda_fp16.h>
#include <cstdint>

#define B_ 8
#define N_ 1024
#define H_ 8
#define D_ 32
#define XN (8192 * 256)
#define WN (256 * 768)
#define NHD (B_ * H_ * N_ * D_)

// Q (pre-scaled by log2(e)/sqrt(D)), K, V: plain fp16
__device__ __half g_qh[NHD], g_k16[NHD], g_v16[NHD];
// plain fp16 GEMM operands
__device__ __half g_xf[XN], g_wf[WN];

// ---------------------------------------------------------------------------
// PTX helpers
// ---------------------------------------------------------------------------
__device__ __forceinline__ uint32_t sptr(const void* p) {
    return (uint32_t)__cvta_generic_to_shared(p);
}
__device__ __forceinline__ void ldmx4(uint32_t* r, uint32_t a) {
    asm volatile("ldmatrix.sync.aligned.m8n8.x4.shared.b16 {%0,%1,%2,%3}, [%4];"
                 : "=r"(r[0]), "=r"(r[1]), "=r"(r[2]), "=r"(r[3]) : "r"(a));
}
__device__ __forceinline__ void ldmx4t(uint32_t* r, uint32_t a) {
    asm volatile("ldmatrix.sync.aligned.m8n8.x4.trans.shared.b16 {%0,%1,%2,%3}, [%4];"
                 : "=r"(r[0]), "=r"(r[1]), "=r"(r[2]), "=r"(r[3]) : "r"(a));
}
__device__ __forceinline__ void ldmx2t(uint32_t* r, uint32_t a) {
    asm volatile("ldmatrix.sync.aligned.m8n8.x2.trans.shared.b16 {%0,%1}, [%2];"
                 : "=r"(r[0]), "=r"(r[1]) : "r"(a));
}
__device__ __forceinline__ void mma_f16(float* d, const uint32_t* a,
                                        uint32_t b0, uint32_t b1) {
    asm volatile("mma.sync.aligned.m16n8k16.row.col.f32.f16.f16.f32 "
                 "{%0,%1,%2,%3}, {%4,%5,%6,%7}, {%8,%9}, {%0,%1,%2,%3};"
                 : "+f"(d[0]), "+f"(d[1]), "+f"(d[2]), "+f"(d[3])
                 : "r"(a[0]), "r"(a[1]), "r"(a[2]), "r"(a[3]), "r"(b0), "r"(b1));
}
// pack two fp32 -> f16x2 (first arg -> low half)
__device__ __forceinline__ uint32_t packh(float lo, float hi) {
    uint32_t r;
    asm("cvt.rn.f16x2.f32 %0, %1, %2;" : "=r"(r) : "f"(hi), "f"(lo));
    return r;
}
__device__ __forceinline__ float ex2(float x) {
    float r;
    asm("ex2.approx.ftz.f32 %0, %1;" : "=f"(r) : "f"(x));
    return r;
}
__device__ __forceinline__ void cpa16(uint32_t dst, const void* src) {
    asm volatile("cp.async.cg.shared.global [%0], [%1], 16;" :: "r"(dst), "l"(src));
}
#define CP_COMMIT asm volatile("cp.async.commit_group;")
#define CP_WAIT0  asm volatile("cp.async.wait_group 0;")
#define CP_WAIT1  asm volatile("cp.async.wait_group 1;")

// ---------------------------------------------------------------------------
// Kernel 0: convert x and W to plain fp16.
// ---------------------------------------------------------------------------
__global__ __launch_bounds__(256) void conv_xw(
    const float* __restrict__ x, const float* __restrict__ W)
{
    int i4 = (blockIdx.x * 256 + threadIdx.x) * 4;
    const float* src;
    __half* dst;
    int off;
    if (i4 < XN) {
        src = x; dst = g_xf; off = i4;
    } else {
        off = i4 - XN;
        if (off >= WN) return;
        src = W; dst = g_wf;
    }
    float4 v = *(const float4*)(src + off);
    *(uint2*)&dst[off] = make_uint2(packh(v.x, v.y), packh(v.z, v.w));
}

// ---------------------------------------------------------------------------
// Kernel 1: QKV projection, plain-fp16 MMA (1 MMA per tile), 3-stage pipeline.
// Epilogue: Q scaled by log2(e)/sqrt(D); Q,K,V all plain fp16.
// Stage = {xf 5120B, wf 4608B} = 9728 B.
// ---------------------------------------------------------------------------
__global__ __launch_bounds__(256) void qkv_gemm_mma(const float* __restrict__ bias)
{
    extern __shared__ __align__(16) unsigned char smg[];
    const int tid = threadIdx.x;
    const int w = tid >> 5, l = tid & 31;
    const int l16 = l & 15;
    const int mw = 32 * (w & 1);
    const int nw = 16 * (w >> 1);
    const int rb = blockIdx.y * 64;
    const int cb = blockIdx.x * 64;

    const int xrow = tid >> 2, xpart = tid & 3;
    const int wrow = tid >> 3, wpart = tid & 7;

    auto stage = [&](int k0, unsigned char* buf) {
        cpa16(sptr(buf + xrow * 80 + xpart * 16),
              g_xf + (size_t)(rb + xrow) * 256 + k0 + xpart * 8);
        cpa16(sptr(buf + 5120 + wrow * 144 + wpart * 16),
              g_wf + (size_t)(k0 + wrow) * 768 + cb + wpart * 8);
    };

    float acc[2][2][4] = {};

    stage(0, smg);           CP_COMMIT;
    stage(32, smg + 9728);   CP_COMMIT;

    for (int c = 0; c < 8; c++) {
        if (c < 7) { CP_WAIT1; } else { CP_WAIT0; }
        __syncthreads();
        if (c < 6) {
            stage((c + 2) * 32, smg + ((c + 2) % 3) * 9728);
            CP_COMMIT;
        }
        unsigned char* buf = smg + (c % 3) * 9728;
        const __half* xf = (const __half*)(buf);
        const __half* wf = (const __half*)(buf + 5120);

        #pragma unroll
        for (int ks = 0; ks < 2; ks++) {
            uint32_t af[2][4];
            #pragma unroll
            for (int mf = 0; mf < 2; mf++) {
                int aoff = (mw + 16 * mf + l16) * 40 + ks * 16 + ((l & 16) >> 1);
                ldmx4(af[mf], sptr(xf + aoff));
            }
            #pragma unroll
            for (int t = 0; t < 2; t++) {
                int woff = (ks * 16 + l16) * 72 + nw + 8 * t;
                uint32_t bf[2];
                ldmx2t(bf, sptr(wf + woff));
                #pragma unroll
                for (int mf = 0; mf < 2; mf++)
                    mma_f16(acc[mf][t], af[mf], bf[0], bf[1]);
            }
        }
    }

    // Q scale folds 1/sqrt(32) AND log2(e) so attention can use ex2 directly
    const float QSCALE = 0.17677669529663687f * 1.4426950408889634f;

    #pragma unroll
    for (int t = 0; t < 2; t++) {
        int c0 = cb + nw + 8 * t + 2 * (l & 3);
        int s = c0 >> 8, rem = c0 & 255, h = rem >> 5, d = rem & 31;
        float sc = (s == 0) ? QSCALE : 1.0f;
        float b0 = bias[c0], b1 = bias[c0 + 1];
        __half* dst = (s == 0) ? g_qh : (s == 1) ? g_k16 : g_v16;
        #pragma unroll
        for (int mf = 0; mf < 2; mf++) {
            #pragma unroll
            for (int rr = 0; rr < 2; rr++) {
                int r = rb + mw + 16 * mf + (l >> 2) + 8 * rr;
                int bq = r >> 10, n = r & 1023;
                float v0 = (acc[mf][t][2 * rr + 0] + b0) * sc;
                float v1 = (acc[mf][t][2 * rr + 1] + b1) * sc;
                size_t idx = ((size_t)(bq * 8 + h) * 1024 + n) * 32 + d;
                *(uint32_t*)&dst[idx] = packh(v0, v1);
            }
        }
    }
}

// ---------------------------------------------------------------------------
// Kernel 2: tensor-core moire attention, all plain fp16:
//  - QK: Q @ K, 8 MMAs/iter; PV: P @ V, 8 MMAs/iter
//  - log2-domain exponents, weights re-centered +15 octaves (fp16 normal range)
// Layout: [0,8192) Q region (Qh in first 4096; Obuf overlays full 8192 post-loop)
//         [8192, +3*10240): stages {Kf 5120, Vf 5120}; lsum overlays stage 0.
// ---------------------------------------------------------------------------
__global__ __launch_bounds__(256, 2) void moire_attn(
    const float* __restrict__ adj, const unsigned int* __restrict__ mask,
    const float* __restrict__ shifts, const float* __restrict__ widths,
    const float* __restrict__ slw, float* __restrict__ out)
{
    extern __shared__ __align__(16) unsigned char smraw[];

    const int hh = blockIdx.x;
    const int q0 = blockIdx.y * 64;
    const int bb = blockIdx.z;
    const int tid = threadIdx.x;
    const int w   = tid >> 5;
    const int l   = tid & 31;
    const int wm  = w & 3;
    const int wk  = w >> 2;
    const int m0  = 16 * wm;
    const int n0k = 32 * wk;
    const int l16 = l & 15;
    const int qal = m0 + (l >> 2);
    const int qbl = qal + 8;

    const float LOG2E = 1.4426950408889634f;
    const float sh    = shifts[hh];
    const float invw2 = LOG2E / fmaxf(widths[hh], 0.5f);
    const float sl2   = slw[hh] * LOG2E;
    const float LOGEPS2 = -19.931568569324174f;   // log2(1e-6)

    const size_t hbase = ((size_t)(bb * 8 + hh)) * 1024 * 32;

    __half* Qh = (__half*)(smraw);

    const int row = tid >> 2, part = tid & 3;

    auto stageKV = [&](int kb, unsigned char* buf) {
        size_t g = hbase + (size_t)(kb + row) * 32 + part * 8;
        cpa16(sptr(buf + row * 80 + part * 16),        g_k16 + g);
        cpa16(sptr(buf + 5120 + row * 80 + part * 16), g_v16 + g);
    };

    // stage Q (plain LDG) + prefetch stages 0,1 of K/V
    {
        size_t gq = hbase + (size_t)(q0 + row) * 32 + part * 8;
        *(uint4*)(Qh + row * 32 + part * 8) = *(const uint4*)(g_qh + gq);
    }
    stageKV(0, smraw + 8192);            CP_COMMIT;
    stageKV(64, smraw + 8192 + 10240);   CP_COMMIT;

    const float fqa = (mask[(size_t)bb * 1024 + q0 + qal] != 0u) ? 1.0f : 0.0f;
    const float fqb = (mask[(size_t)bb * 1024 + q0 + qbl] != 0u) ? 1.0f : 0.0f;
    __syncthreads();

    uint32_t qfh[2][4];
    #pragma unroll
    for (int ks = 0; ks < 2; ks++) {
        int off = (m0 + l16) * 32 + ks * 16 + ((l & 16) >> 1);
        ldmx4(qfh[ks], sptr(Qh + off));
    }

    // V ldmatrix.x4.trans lane address components
    const int vmi = l >> 3, vr = l & 7;
    const int vrow_off = (vmi & 1) * 8 + vr;     // k within 16
    const int vcol_off = 8 * (vmi >> 1);         // second n8 tile select

    float Oacc[4][4] = {};
    float lsa = 0.0f, lsb = 0.0f;

    for (int it = 0; it < 16; it++) {
        const int kb = it * 64;
        // adj + mask prefetch (regs; overlaps pipeline drain)
        float2 av[2][4];
        uint2  mkp[4];
        {
            const float* ap = adj + ((size_t)(bb * 1024 + q0 + qal)) * 1024
                              + kb + n0k + 2 * (l & 3);
            const unsigned int* mp = mask + (size_t)bb * 1024 + kb + n0k + 2 * (l & 3);
            #pragma unroll
            for (int t = 0; t < 4; t++) {
                av[0][t] = *(const float2*)(ap + 8 * t);
                av[1][t] = *(const float2*)(ap + 8 * 1024 + 8 * t);
                mkp[t]   = *(const uint2*)(mp + 8 * t);
            }
        }
        if (it < 15) { CP_WAIT1; } else { CP_WAIT0; }
        __syncthreads();   // stage `it` visible to all; iter it-1 reads done
        if (it < 14) {
            stageKV(kb + 128, smraw + 8192 + ((it + 2) % 3) * 10240);
            CP_COMMIT;
        }

        unsigned char* buf = smraw + 8192 + (it % 3) * 10240;
        const __half* Kf = (const __half*)(buf);
        const __half* Vf = (const __half*)(buf + 5120);

        // ---- QK: 4 n8-tile accumulators; Q @ K, K frags via x4 ----
        float acc[4][4] = {};
        #pragma unroll
        for (int ks = 0; ks < 2; ks++) {
            #pragma unroll
            for (int t2 = 0; t2 < 2; t2++) {
                int koff = (n0k + 16 * t2 + l16) * 40 + ks * 16 + ((l & 16) >> 1);
                uint32_t rh[4];
                ldmx4(rh, sptr(Kf + koff));
                mma_f16(acc[2 * t2],     qfh[ks], rh[0], rh[2]);
                mma_f16(acc[2 * t2 + 1], qfh[ks], rh[1], rh[3]);
            }
        }

        // ---- elementwise (log2-domain): moire + self-loop + mask + ex2 ----
        const bool diag = (kb == q0);
        #pragma unroll
        for (int t = 0; t < 4; t++) {
            int c0 = n0k + 8 * t + 2 * (l & 3);
            float kb0 = (mkp[t].x != 0u) ? -17.312340490667560f : -1442712.4f;
            float kb1 = (mkp[t].y != 0u) ? -17.312340490667560f : -1442712.4f;
            float ax = av[0][t].x - sh, ay = av[0][t].y - sh;
            float bx = av[1][t].x - sh, by = av[1][t].y - sh;
            float v00 = acc[t][0] + fmaxf(-ax * ax * invw2, LOGEPS2);
            float v01 = acc[t][1] + fmaxf(-ay * ay * invw2, LOGEPS2);
            float v10 = acc[t][2] + fmaxf(-bx * bx * invw2, LOGEPS2);
            float v11 = acc[t][3] + fmaxf(-by * by * invw2, LOGEPS2);
            if (diag) {
                if (qal == c0)     v00 += sl2;
                if (qal == c0 + 1) v01 += sl2;
                if (qbl == c0)     v10 += sl2;
                if (qbl == c0 + 1) v11 += sl2;
            }
            // +15 octaves re-centers weights into fp16 normal range;
            // the 2^15 scale cancels in Oacc/lsum.
            float w00 = ex2(fqa * (v00 + kb0) + 15.0f);
            float w01 = ex2(fqa * (v01 + kb1) + 15.0f);
            float w10 = ex2(fqb * (v10 + kb0) + 15.0f);
            float w11 = ex2(fqb * (v11 + kb1) + 15.0f);
            lsa += w00 + w01;
            lsb += w10 + w11;
            acc[t][0] = w00; acc[t][1] = w01; acc[t][2] = w10; acc[t][3] = w11;
        }

        // ---- P fragments: plain fp16 (re-centered; rel err 2^-11) ----
        uint32_t pfh[2][4];
        #pragma unroll
        for (int cch = 0; cch < 2; cch++) {
            #pragma unroll
            for (int rr = 0; rr < 2; rr++) {
                const float* a4 = acc[2 * cch + rr];
                pfh[cch][rr * 2 + 0] = packh(a4[0], a4[1]);
                pfh[cch][rr * 2 + 1] = packh(a4[2], a4[3]);
            }
        }

        // ---- PV: O += P@V (fp16); V frags via x4.trans ----
        #pragma unroll
        for (int cch = 0; cch < 2; cch++) {
            #pragma unroll
            for (int tdp = 0; tdp < 2; tdp++) {
                int voff = (n0k + 16 * cch + vrow_off) * 40 + 8 * (2 * tdp) + vcol_off;
                uint32_t rv[4];
                ldmx4t(rv, sptr(Vf + voff));
                mma_f16(Oacc[2 * tdp],     pfh[cch], rv[0], rv[1]);
                mma_f16(Oacc[2 * tdp + 1], pfh[cch], rv[2], rv[3]);
            }
        }
    }

    // ---- lsum: zero (overlay on stage area), reduce, accumulate ----
    __syncthreads();
    float* lsum = (float*)(smraw + 8192);
    if (tid < 64) lsum[tid] = 0.0f;
    __syncthreads();
    lsa += __shfl_xor_sync(0xffffffffu, lsa, 1);
    lsa += __shfl_xor_sync(0xffffffffu, lsa, 2);
    lsb += __shfl_xor_sync(0xffffffffu, lsb, 1);
    lsb += __shfl_xor_sync(0xffffffffu, lsb, 2);
    if ((l & 3) == 0) {
        atomicAdd(&lsum[qal], lsa);
        atomicAdd(&lsum[qbl], lsb);
    }

    // ---- combine wk halves via Obuf (overlays Q region) and write out ----
    float* Obuf = (float*)smraw;  // 64 x 32 floats = 8KB
    if (wk == 1) {
        #pragma unroll
        for (int td = 0; td < 4; td++) {
            int n = 8 * td + 2 * (l & 3);
            *(float2*)&Obuf[qal * 32 + n] = make_float2(Oacc[td][0], Oacc[td][1]);
            *(float2*)&Obuf[qbl * 32 + n] = make_float2(Oacc[td][2], Oacc[td][3]);
        }
    }
    __syncthreads();
    if (wk == 0) {
        float rla = 1.0f / lsum[qal];
        float rlb = 1.0f / lsum[qbl];
        #pragma unroll
        for (int td = 0; td < 4; td++) {
            int n = 8 * td + 2 * (l & 3);
            float2 oa = *(const float2*)&Obuf[qal * 32 + n];
            float2 ob = *(const float2*)&Obuf[qbl * 32 + n];
            oa.x = (oa.x + Oacc[td][0]) * rla;
            oa.y = (oa.y + Oacc[td][1]) * rla;
            ob.x = (ob.x + Oacc[td][2]) * rlb;
            ob.y = (ob.y + Oacc[td][3]) * rlb;
            *(float2*)&out[((size_t)bb * 1024 + q0 + qal) * 256 + hh * 32 + n] = oa;
            *(float2*)&out[((size_t)bb * 1024 + q0 + qbl) * 256 + hh * 32 + n] = ob;
        }
    }
}

// ---------------------------------------------------------------------------
// Launch. Inputs: x, adj, mask, W_qkv, b_qkv, shifts, widths, self_loop_w
// ---------------------------------------------------------------------------
extern "C" void kernel_launch(void* const* d_in, const int* in_sizes, int n_in,
                              void* d_out, int out_size)
{
    const float*        x      = (const float*)d_in[0];
    const float*        adj    = (const float*)d_in[1];
    const unsigned int* mask   = (const unsigned int*)d_in[2];
    const float*        W_qkv  = (const float*)d_in[3];
    const float*        b_qkv  = (const float*)d_in[4];
    const float*        shifts = (const float*)d_in[5];
    const float*        widths = (const float*)d_in[6];
    const float*        slw    = (const float*)d_in[7];
    float*              out    = (float*)d_out;

    static bool attr_done = false;
    if (!attr_done) {
        cudaFuncSetAttribute(qkv_gemm_mma,
            cudaFuncAttributeMaxDynamicSharedMemorySize, 3 * 9728);
        cudaFuncSetAttribute(moire_attn,
            cudaFuncAttributeMaxDynamicSharedMemorySize, 8192 + 3 * 10240);
        attr_done = true;
    }

    conv_xw<<<(XN + WN) / 1024, 256>>>(x, W_qkv);
    qkv_gemm_mma<<<dim3(12, 128), 256, 3 * 9728>>>(b_qkv);
    moire_attn<<<dim3(8, 16, 8), 256, 8192 + 3 * 10240>>>(
        adj, mask, shifts, widths, slw, out);
}